// round 12
// baseline (speedup 1.0000x reference)
#include <cuda_runtime.h>
#include <cuda_bf16.h>
#include <cuda_fp16.h>
#include <math.h>
#include <stdint.h>
#include <stddef.h>

#define NB 2
#define NS 2048
#define NC 2048
#define ND 128
#define NH 16
#define NM (NB * NS)       // 4096
#define NBH (NB * NH)      // 32
#define RMS_EPS 1.1920928955078125e-07f
#define SM_SCALE 0.08838834764831844f

typedef __half f16;

// ---------------- scratch (device globals; no allocation) ----------------
__device__ float g_q[(size_t)NM * NC];
__device__ float g_k[(size_t)NM * NC];
__device__ float g_v[(size_t)NM * NC];

// f16 operands
__device__ f16 g_xhf[(size_t)NM * NC], g_xlf[(size_t)NM * NC];
__device__ f16 g_wqf[(size_t)NC * NC], g_wkf[(size_t)NC * NC];
__device__ f16 g_wvf[(size_t)NC * NC], g_wof[(size_t)NC * NC];
__device__ f16 g_vtf[(size_t)NB * NC * NS];
__device__ f16 g_chf[(size_t)NM * NC], g_clf[(size_t)NM * NC];
__device__ f16 g_qhf[(size_t)NM * NC], g_qlf[(size_t)NM * NC];   // Q split 2xf16
__device__ f16 g_kf[(size_t)NM * NC];                            // K single f16

// ---------------- PTX helpers (sm_80-era, family-target safe) -------------
__device__ __forceinline__ uint32_t smem_to_u32(const void* p) {
    uint32_t a;
    asm("{ .reg .u64 t; cvta.to.shared.u64 t, %1; cvt.u32.u64 %0, t; }"
        : "=r"(a) : "l"(p));
    return a;
}
__device__ __forceinline__ void cp_async16(uint32_t dst, const void* src) {
    asm volatile("cp.async.cg.shared.global [%0], [%1], 16;"
                 :: "r"(dst), "l"(src) : "memory");
}
__device__ __forceinline__ void cp_commit() {
    asm volatile("cp.async.commit_group;" ::: "memory");
}
template <int N>
__device__ __forceinline__ void cp_wait() {
    asm volatile("cp.async.wait_group %0;" :: "n"(N) : "memory");
}
__device__ __forceinline__ void ldm_x4(uint32_t (&r)[4], uint32_t addr) {
    asm volatile("ldmatrix.sync.aligned.m8n8.x4.shared.b16 {%0,%1,%2,%3}, [%4];"
                 : "=r"(r[0]), "=r"(r[1]), "=r"(r[2]), "=r"(r[3]) : "r"(addr));
}
__device__ __forceinline__ void mma_f16(float (&d)[4], const uint32_t (&a)[4],
                                        uint32_t b0, uint32_t b1) {
    asm volatile("mma.sync.aligned.m16n8k16.row.col.f32.f16.f16.f32 "
                 "{%0,%1,%2,%3}, {%4,%5,%6,%7}, {%8,%9}, {%0,%1,%2,%3};"
                 : "+f"(d[0]), "+f"(d[1]), "+f"(d[2]), "+f"(d[3])
                 : "r"(a[0]), "r"(a[1]), "r"(a[2]), "r"(a[3]), "r"(b0), "r"(b1));
}

__device__ __forceinline__ void split2f(float x, f16& h, f16& l) {
    h = __float2half_rn(x);
    l = __float2half_rn(x - __half2float(h));
}
__device__ __forceinline__ uint32_t pack_f16x2(float x, float y) {
    __half2 H = __floats2half2_rn(x, y);
    return *reinterpret_cast<uint32_t*>(&H);
}

// ---------------- common tiling constants ----------------
#define KCH 32
#define ROW_BYTES 80
#define TILE_BYTES (128 * ROW_BYTES)        // 10240

// =========================================================================
// f16 2-term GEMM (QKV + out-proj): A split 2xf16, B single f16.
// 512 threads, warp tile 16x64, 3-stage cp.async pipeline.
// =========================================================================
#define F16_STAGE (3 * TILE_BYTES)          // 30720
#define F16_SMEM (3 * F16_STAGE)            // 92160

// 512 threads: one 16B chunk per thread per tile (128 rows x 4 chunks)
__device__ __forceinline__ void load_tile_512(uint32_t smbase, const void* g,
                                              int ld, int k0, int tid) {
    const char* gp = (const char*)g + (size_t)k0 * 2;
    int row = tid >> 2;
    int c = tid & 3;
    cp_async16(smbase + row * ROW_BYTES + c * 16,
               gp + (size_t)row * ld * 2 + c * 16);
}

__global__ __launch_bounds__(512)
void k_gemm_nt_f16(const f16* __restrict__ AhG, const f16* __restrict__ AlG,
                   const f16* __restrict__ BfG, const float* __restrict__ biasG,
                   float* __restrict__ OutG)
{
    size_t bm = (size_t)blockIdx.y * 128;
    size_t bn = (size_t)blockIdx.x * 128;
    const f16* Ah = AhG + bm * NC;
    const f16* Al = AlG + bm * NC;
    const f16* Bf = BfG + bn * NC;
    const float* bias = biasG + bn;
    float* Out = OutG + bm * NC + bn;

    extern __shared__ char sm[];
    uint32_t sb = smem_to_u32(sm);
    const int tid = threadIdx.x;             // 512 threads = 16 warps
    const int lane = tid & 31;
    const int warp = tid >> 5;
    const int wm = warp >> 1;                // 0..7  rows: wm*16
    const int wn = warp & 1;                 // 0..1  cols: wn*64

    float acc[8][4];
    #pragma unroll
    for (int nt = 0; nt < 8; nt++)
        #pragma unroll
        for (int j = 0; j < 4; j++) acc[nt][j] = 0.0f;

    const int nch = NC / KCH;

    auto load_chunk = [&](int ch, int s) {
        uint32_t base = sb + s * F16_STAGE;
        int k0 = ch * KCH;
        load_tile_512(base,                  Ah, NC, k0, tid);
        load_tile_512(base + TILE_BYTES,     Al, NC, k0, tid);
        load_tile_512(base + 2 * TILE_BYTES, Bf, NC, k0, tid);
    };

    load_chunk(0, 0);
    cp_commit();
    load_chunk(1, 1);
    cp_commit();

    int stage = 0;
    for (int ch = 0; ch < nch; ch++) {
        if (ch + 1 < nch) cp_wait<1>(); else cp_wait<0>();
        __syncthreads();
        if (ch + 2 < nch) {
            int ns = stage + 2;
            if (ns >= 3) ns -= 3;
            load_chunk(ch + 2, ns);
            cp_commit();
        }

        uint32_t base = sb + stage * F16_STAGE;
        if (++stage == 3) stage = 0;

        #pragma unroll
        for (int ks = 0; ks < 2; ks++) {
            uint32_t koff = (uint32_t)(ks * 32 + (lane >> 4) * 16);
            uint32_t ah[4], al[4];
            {
                uint32_t r = wm * 16 + (lane & 15);
                uint32_t addr = base + r * ROW_BYTES + koff;
                ldm_x4(ah, addr);
                ldm_x4(al, addr + TILE_BYTES);
            }
            uint32_t bfr[4][4];
            #pragma unroll
            for (int ng = 0; ng < 4; ng++) {
                uint32_t r = wn * 64 + ng * 16 + (lane & 15);
                ldm_x4(bfr[ng], base + 2 * TILE_BYTES + r * ROW_BYTES + koff);
            }
            #pragma unroll
            for (int ng = 0; ng < 4; ng++) {
                mma_f16(acc[2 * ng],     ah, bfr[ng][0], bfr[ng][2]);
                mma_f16(acc[2 * ng],     al, bfr[ng][0], bfr[ng][2]);
                mma_f16(acc[2 * ng + 1], ah, bfr[ng][1], bfr[ng][3]);
                mma_f16(acc[2 * ng + 1], al, bfr[ng][1], bfr[ng][3]);
            }
        }
    }

    int r0 = wm * 16 + (lane >> 2);
    #pragma unroll
    for (int nt = 0; nt < 8; nt++) {
        int c = wn * 64 + nt * 8 + (lane & 3) * 2;
        float bx = bias[c], by = bias[c + 1];
        float2 v0 = { acc[nt][0] + bx, acc[nt][1] + by };
        float2 v1 = { acc[nt][2] + bx, acc[nt][3] + by };
        *(float2*)(Out + (size_t)r0 * NC + c) = v0;
        *(float2*)(Out + (size_t)(r0 + 8) * NC + c) = v1;
    }
}

// =========================================================================
// Flash attention: scores (f16 2-term) + online softmax + PV (f16 1-term)
// Double-buffered K AND V (unchanged from R11).
// =========================================================================
#define FT_ROWB 272                          // 256B row + 16B pad
#define FT_TILE (128 * FT_ROWB)              // 34816
#define OFF_K 0
#define OFF_V (2 * FT_TILE)
#define FLASH_SMEM (4 * FT_TILE)             // 139264

__device__ __forceinline__ void fa_load_one(uint32_t dst, const f16* g,
                                            size_t rowbase, size_t ldrow, int tid)
{
    #pragma unroll
    for (int i = 0; i < 8; i++) {
        int idx = tid + i * 256;
        int row = idx >> 4;
        int ch = idx & 15;
        cp_async16(dst + row * FT_ROWB + ch * 16,
                   (const char*)(g + rowbase + (size_t)row * ldrow) + ch * 16);
    }
}

__global__ void __launch_bounds__(256, 1) k_flash()
{
    extern __shared__ char sm[];
    uint32_t sb = smem_to_u32(sm);
    const int tid = threadIdx.x;
    const int lane = tid & 31;
    const int warp = tid >> 5;
    const int q0 = blockIdx.x * 128;
    const int bh = blockIdx.y, b = bh >> 4, h = bh & 15;

    const size_t kbase = (size_t)(b * NS) * NC + (size_t)h * ND;
    const size_t vbase = ((size_t)b * NC + (size_t)h * ND) * NS;

    // ---- stage Q hi/lo through buffers K0/V0; K0&V0 data go to buffer 1 ----
    size_t qbase = (size_t)(b * NS + q0) * NC + (size_t)h * ND;
    fa_load_one(sb + OFF_K, g_qhf, qbase, NC, tid);
    fa_load_one(sb + OFF_V, g_qlf, qbase, NC, tid);
    cp_commit();                                        // group: Q
    fa_load_one(sb + OFF_K + FT_TILE, g_kf, kbase, NC, tid);
    fa_load_one(sb + OFF_V + FT_TILE, g_vtf, vbase, NS, tid);
    cp_commit();                                        // group: K0,V0
    cp_wait<1>();                                       // Q ready
    __syncthreads();

    uint32_t qhf[8][4], qlf[8][4];
    {
        uint32_t rbase = sb + (warp * 16 + (lane & 15)) * FT_ROWB + ((lane >> 4) << 4);
        #pragma unroll
        for (int ks = 0; ks < 8; ks++) {
            ldm_x4(qhf[ks], rbase + OFF_K + ks * 32);
            ldm_x4(qlf[ks], rbase + OFF_V + ks * 32);
        }
    }
    __syncthreads();                                    // Q buffers free

    fa_load_one(sb + OFF_K, g_kf, kbase + (size_t)128 * NC, NC, tid);
    fa_load_one(sb + OFF_V, g_vtf, vbase + 128, NS, tid);
    cp_commit();                                        // group: K1,V1

    float o[16][4];
    #pragma unroll
    for (int i = 0; i < 16; i++) { o[i][0] = 0.f; o[i][1] = 0.f; o[i][2] = 0.f; o[i][3] = 0.f; }
    float m0 = -1e30f, m1 = -1e30f, l0 = 0.f, l1 = 0.f;

    for (int j = 0; j < 16; j++) {
        // groups pending: {KV_j, KV_{j+1}} -> wait for KV_j
        if (j + 1 < 16) cp_wait<1>(); else cp_wait<0>();
        __syncthreads();

        uint32_t bufo = (uint32_t)((j + 1) & 1) * FT_TILE;

        // (B) S = Q @ K_j^T  (f16 2-term)
        float s[16][4];
        #pragma unroll
        for (int i = 0; i < 16; i++) { s[i][0] = 0.f; s[i][1] = 0.f; s[i][2] = 0.f; s[i][3] = 0.f; }
        #pragma unroll
        for (int ng = 0; ng < 8; ng++) {
            #pragma unroll
            for (int ks = 0; ks < 8; ks++) {
                uint32_t addr = sb + OFF_K + bufo + (ng * 16 + (lane & 15)) * FT_ROWB
                              + ((lane >> 4) << 4) + ks * 32;
                uint32_t kf4[4];
                ldm_x4(kf4, addr);
                mma_f16(s[2 * ng],     qhf[ks], kf4[0], kf4[2]);
                mma_f16(s[2 * ng],     qlf[ks], kf4[0], kf4[2]);
                mma_f16(s[2 * ng + 1], qhf[ks], kf4[1], kf4[3]);
                mma_f16(s[2 * ng + 1], qlf[ks], kf4[1], kf4[3]);
            }
        }

        // (D) online softmax: p = exp((s - m)*scale) <= 1 (f16-safe by construction)
        float mx0 = -1e30f, mx1 = -1e30f;
        #pragma unroll
        for (int i = 0; i < 16; i++) {
            mx0 = fmaxf(mx0, fmaxf(s[i][0], s[i][1]));
            mx1 = fmaxf(mx1, fmaxf(s[i][2], s[i][3]));
        }
        mx0 = fmaxf(mx0, __shfl_xor_sync(0xffffffffu, mx0, 1));
        mx0 = fmaxf(mx0, __shfl_xor_sync(0xffffffffu, mx0, 2));
        mx1 = fmaxf(mx1, __shfl_xor_sync(0xffffffffu, mx1, 1));
        mx1 = fmaxf(mx1, __shfl_xor_sync(0xffffffffu, mx1, 2));
        float nm0 = fmaxf(m0, mx0), nm1 = fmaxf(m1, mx1);
        float a0 = __expf((m0 - nm0) * SM_SCALE);
        float a1 = __expf((m1 - nm1) * SM_SCALE);
        m0 = nm0; m1 = nm1;
        float ps0 = 0.f, ps1 = 0.f;
        #pragma unroll
        for (int i = 0; i < 16; i++) {
            s[i][0] = __expf((s[i][0] - m0) * SM_SCALE);
            s[i][1] = __expf((s[i][1] - m0) * SM_SCALE);
            s[i][2] = __expf((s[i][2] - m1) * SM_SCALE);
            s[i][3] = __expf((s[i][3] - m1) * SM_SCALE);
            ps0 += s[i][0] + s[i][1];
            ps1 += s[i][2] + s[i][3];
        }
        l0 = l0 * a0 + ps0;
        l1 = l1 * a1 + ps1;
        #pragma unroll
        for (int i = 0; i < 16; i++) {
            o[i][0] *= a0; o[i][1] *= a0; o[i][2] *= a1; o[i][3] *= a1;
        }

        // (F) ctx += P @ V_j  (P single f16 in [0,1], V single f16)
        #pragma unroll
        for (int ks = 0; ks < 8; ks++) {
            uint32_t pa[4];
            pa[0] = pack_f16x2(s[2 * ks][0],     s[2 * ks][1]);
            pa[1] = pack_f16x2(s[2 * ks][2],     s[2 * ks][3]);
            pa[2] = pack_f16x2(s[2 * ks + 1][0], s[2 * ks + 1][1]);
            pa[3] = pack_f16x2(s[2 * ks + 1][2], s[2 * ks + 1][3]);
            #pragma unroll
            for (int ng = 0; ng < 8; ng++) {
                uint32_t addr = sb + OFF_V + bufo + (ng * 16 + (lane & 15)) * FT_ROWB
                              + ((lane >> 4) << 4) + ks * 32;
                uint32_t vf4[4];
                ldm_x4(vf4, addr);
                mma_f16(o[2 * ng],     pa, vf4[0], vf4[2]);
                mma_f16(o[2 * ng + 1], pa, vf4[1], vf4[3]);
            }
        }

        // (G) buffers for iter j are free -> start K_{j+2}, V_{j+2} into them
        __syncthreads();
        if (j + 2 < 16) {
            fa_load_one(sb + OFF_K + bufo, g_kf,
                        kbase + (size_t)(j + 2) * 128 * NC, NC, tid);
            fa_load_one(sb + OFF_V + bufo, g_vtf,
                        vbase + (size_t)(j + 2) * 128, NS, tid);
            cp_commit();
        }
    }

    // ---- finalize: normalize, split to f16 hi/lo, write ctx ----
    l0 += __shfl_xor_sync(0xffffffffu, l0, 1);
    l0 += __shfl_xor_sync(0xffffffffu, l0, 2);
    l1 += __shfl_xor_sync(0xffffffffu, l1, 1);
    l1 += __shfl_xor_sync(0xffffffffu, l1, 2);
    float i0 = 1.0f / l0, i1 = 1.0f / l1;

    size_t gr0 = (size_t)(b * NS + q0 + warp * 16 + (lane >> 2));
    #pragma unroll
    for (int nt = 0; nt < 16; nt++) {
        int c = h * ND + nt * 8 + (lane & 3) * 2;
        f16 h0, h1, lo0, lo1;
        split2f(o[nt][0] * i0, h0, lo0);
        split2f(o[nt][1] * i0, h1, lo1);
        *(__half2*)(g_chf + gr0 * NC + c) = __half2{h0, h1};
        *(__half2*)(g_clf + gr0 * NC + c) = __half2{lo0, lo1};
        split2f(o[nt][2] * i1, h0, lo0);
        split2f(o[nt][3] * i1, h1, lo1);
        *(__half2*)(g_chf + (gr0 + 8) * NC + c) = __half2{h0, h1};
        *(__half2*)(g_clf + (gr0 + 8) * NC + c) = __half2{lo0, lo1};
    }
}

// ---------------- elementwise kernels ----------------
__global__ __launch_bounds__(256) void cvt_split_f16(const float* __restrict__ src,
                                                     f16* __restrict__ hi,
                                                     f16* __restrict__ lo)
{
    size_t i = (size_t)blockIdx.x * 256 + threadIdx.x;
    float4 v = ((const float4*)src)[i];
    f16 h0, h1, h2, h3, l0, l1, l2, l3;
    split2f(v.x, h0, l0); split2f(v.y, h1, l1);
    split2f(v.z, h2, l2); split2f(v.w, h3, l3);
    __half2* hp = (__half2*)hi;
    __half2* lp = (__half2*)lo;
    hp[2 * i]     = __half2{h0, h1};
    hp[2 * i + 1] = __half2{h2, h3};
    lp[2 * i]     = __half2{l0, l1};
    lp[2 * i + 1] = __half2{l2, l3};
}

// Convert the 4 weight matrices in one launch: blockIdx.y selects tensor.
__global__ __launch_bounds__(256) void cvt_f16_w(
    const float* __restrict__ s0, const float* __restrict__ s1,
    const float* __restrict__ s2, const float* __restrict__ s3,
    f16* __restrict__ d0, f16* __restrict__ d1,
    f16* __restrict__ d2, f16* __restrict__ d3)
{
    const float* src = (blockIdx.y == 0) ? s0 : (blockIdx.y == 1) ? s1
                     : (blockIdx.y == 2) ? s2 : s3;
    f16* dst = (blockIdx.y == 0) ? d0 : (blockIdx.y == 1) ? d1
             : (blockIdx.y == 2) ? d2 : d3;
    size_t i = (size_t)blockIdx.x * 256 + threadIdx.x;
    float4 v = ((const float4*)src)[i];
    __half2* dp = (__half2*)dst;
    dp[2 * i]     = __floats2half2_rn(v.x, v.y);
    dp[2 * i + 1] = __floats2half2_rn(v.z, v.w);
}

// V transpose to single f16: g_v[(b*S+s), c] -> vT[(b*C+c), s]
__global__ __launch_bounds__(256) void transpose_v_f16()
{
    __shared__ float t[32][33];
    int b = blockIdx.z;
    int s0 = blockIdx.x * 32, c0 = blockIdx.y * 32;
    int tx = threadIdx.x, ty = threadIdx.y;  // 32 x 8
    #pragma unroll
    for (int j = 0; j < 4; j++) {
        int s = s0 + ty + j * 8;
        t[ty + j * 8][tx] = g_v[((size_t)b * NS + s) * NC + c0 + tx];
    }
    __syncthreads();
    #pragma unroll
    for (int j = 0; j < 4; j++) {
        int c = c0 + ty + j * 8;
        g_vtf[((size_t)b * NC + c) * NS + s0 + tx] = __float2half_rn(t[tx][ty + j * 8]);
    }
}

// Per-head RMSNorm + RoPE; reads fp32 g_q/g_k; writes Q split 2xf16, K single f16.
__global__ __launch_bounds__(256) void rmsnorm_rope(
    const float* __restrict__ rope,
    const float* __restrict__ gq, const float* __restrict__ gk)
{
    int warp = blockIdx.x * 8 + (threadIdx.x >> 5);
    int lane = threadIdx.x & 31;
    int m = warp >> 4;
    int h = warp & 15;
    int s = m & (NS - 1);

    size_t off = (size_t)m * NC + h * ND;
    const float* qr = g_q + off;
    const float* kr = g_k + off;
    const float* rp = rope + (size_t)s * (ND / 2) * 4;
    int d = lane * 4;

    float4 xq = *(const float4*)(qr + d);
    float4 xk = *(const float4*)(kr + d);
    float ssq = xq.x * xq.x + xq.y * xq.y + xq.z * xq.z + xq.w * xq.w;
    float ssk = xk.x * xk.x + xk.y * xk.y + xk.z * xk.z + xk.w * xk.w;
    #pragma unroll
    for (int o = 16; o; o >>= 1) {
        ssq += __shfl_xor_sync(0xffffffffu, ssq, o);
        ssk += __shfl_xor_sync(0xffffffffu, ssk, o);
    }
    float rq = rsqrtf(ssq * (1.0f / ND) + RMS_EPS);
    float rk = rsqrtf(ssk * (1.0f / ND) + RMS_EPS);

    float4 gqv = *(const float4*)(gq + d);
    float4 gkv = *(const float4*)(gk + d);
    xq.x *= rq * gqv.x; xq.y *= rq * gqv.y; xq.z *= rq * gqv.z; xq.w *= rq * gqv.w;
    xk.x *= rk * gkv.x; xk.y *= rk * gkv.y; xk.z *= rk * gkv.z; xk.w *= rk * gkv.w;

    float4 r0 = *(const float4*)(rp + (size_t)(2 * lane) * 4);
    float4 r1 = *(const float4*)(rp + (size_t)(2 * lane + 1) * 4);
    float4 oq, ok;
    oq.x = r0.x * xq.x + r0.y * xq.y;  oq.y = r0.z * xq.x + r0.w * xq.y;
    oq.z = r1.x * xq.z + r1.y * xq.w;  oq.w = r1.z * xq.z + r1.w * xq.w;
    ok.x = r0.x * xk.x + r0.y * xk.y;  ok.y = r0.z * xk.x + r0.w * xk.y;
    ok.z = r1.x * xk.z + r1.y * xk.w;  ok.w = r1.z * xk.z + r1.w * xk.w;

    f16 h0, h1, h2, h3, l0, l1, l2, l3;
    split2f(oq.x, h0, l0); split2f(oq.y, h1, l1);
    split2f(oq.z, h2, l2); split2f(oq.w, h3, l3);
    *(__half2*)(g_qhf + off + d)     = __half2{h0, h1};
    *(__half2*)(g_qhf + off + d + 2) = __half2{h2, h3};
    *(__half2*)(g_qlf + off + d)     = __half2{l0, l1};
    *(__half2*)(g_qlf + off + d + 2) = __half2{l2, l3};

    *(__half2*)(g_kf + off + d)     = __floats2half2_rn(ok.x, ok.y);
    *(__half2*)(g_kf + off + d + 2) = __floats2half2_rn(ok.z, ok.w);
}

// ---------------- launch ----------------
extern "C" void kernel_launch(void* const* d_in, const int* in_sizes, int n_in,
                              void* d_out, int out_size)
{
    const float* x    = (const float*)d_in[0];
    const float* rope = (const float*)d_in[1];
    const float* Wq   = (const float*)d_in[2];
    const float* bq   = (const float*)d_in[3];
    const float* Wk   = (const float*)d_in[4];
    const float* bk   = (const float*)d_in[5];
    const float* Wv   = (const float*)d_in[6];
    const float* bv   = (const float*)d_in[7];
    const float* gq   = (const float*)d_in[8];
    const float* gk   = (const float*)d_in[9];
    const float* Wo   = (const float*)d_in[10];
    const float* bo   = (const float*)d_in[11];
    float* out = (float*)d_out;

    cudaFuncSetAttribute(k_gemm_nt_f16, cudaFuncAttributeMaxDynamicSharedMemorySize, F16_SMEM);
    cudaFuncSetAttribute(k_flash, cudaFuncAttributeMaxDynamicSharedMemorySize, FLASH_SMEM);

    float *qp, *kp, *vp;
    f16 *xhf, *xlf, *wqf, *wkf, *wvf, *wof, *chf, *clf;
    cudaGetSymbolAddress((void**)&qp, g_q);
    cudaGetSymbolAddress((void**)&kp, g_k);
    cudaGetSymbolAddress((void**)&vp, g_v);
    cudaGetSymbolAddress((void**)&xhf, g_xhf); cudaGetSymbolAddress((void**)&xlf, g_xlf);
    cudaGetSymbolAddress((void**)&wqf, g_wqf); cudaGetSymbolAddress((void**)&wkf, g_wkf);
    cudaGetSymbolAddress((void**)&wvf, g_wvf); cudaGetSymbolAddress((void**)&wof, g_wof);
    cudaGetSymbolAddress((void**)&chf, g_chf); cudaGetSymbolAddress((void**)&clf, g_clf);

    const size_t nX = (size_t)NM * NC;       // 8M elems
    const size_t nW = (size_t)NC * NC;       // 4M elems

    cvt_split_f16<<<(unsigned)(nX / 1024), 256>>>(x, xhf, xlf);
    cvt_f16_w<<<dim3((unsigned)(nW / 1024), 4), 256>>>(Wq, Wk, Wv, Wo,
                                                       wqf, wkf, wvf, wof);

    dim3 gProj(NC / 128, NM / 128);          // (16, 32)
    k_gemm_nt_f16<<<gProj, 512, F16_SMEM>>>(xhf, xlf, wqf, bq, qp);
    k_gemm_nt_f16<<<gProj, 512, F16_SMEM>>>(xhf, xlf, wkf, bk, kp);
    k_gemm_nt_f16<<<gProj, 512, F16_SMEM>>>(xhf, xlf, wvf, bv, vp);

    rmsnorm_rope<<<(NM * NH) / 8, 256>>>(rope, gq, gk);
    transpose_v_f16<<<dim3(NS / 32, NC / 32, NB), dim3(32, 8)>>>();

    k_flash<<<dim3(NS / 128, NBH), 256, FLASH_SMEM>>>();

    k_gemm_nt_f16<<<gProj, 512, F16_SMEM>>>(chf, clf, wof, bo, out);
}

// round 13
// speedup vs baseline: 1.0514x; 1.0514x over previous
#include <cuda_runtime.h>
#include <cuda_bf16.h>
#include <cuda_fp16.h>
#include <math.h>
#include <stdint.h>
#include <stddef.h>

#define NB 2
#define NS 2048
#define NC 2048
#define ND 128
#define NH 16
#define NM (NB * NS)       // 4096
#define NBH (NB * NH)      // 32
#define RMS_EPS 1.1920928955078125e-07f
#define SM_SCALE 0.08838834764831844f

typedef __half f16;

// ---------------- scratch (device globals; no allocation) ----------------
__device__ float g_q[(size_t)NM * NC];
__device__ float g_k[(size_t)NM * NC];
__device__ float g_v[(size_t)NM * NC];

// f16 operands
__device__ f16 g_xhf[(size_t)NM * NC], g_xlf[(size_t)NM * NC];
__device__ f16 g_wqf[(size_t)NC * NC], g_wkf[(size_t)NC * NC];
__device__ f16 g_wvf[(size_t)NC * NC], g_wof[(size_t)NC * NC];
__device__ f16 g_vtf[(size_t)NB * NC * NS];
__device__ f16 g_chf[(size_t)NM * NC], g_clf[(size_t)NM * NC];
__device__ f16 g_qhf[(size_t)NM * NC], g_qlf[(size_t)NM * NC];   // Q split 2xf16
__device__ f16 g_kf[(size_t)NM * NC];                            // K single f16

// ---------------- PTX helpers (sm_80-era, family-target safe) -------------
__device__ __forceinline__ uint32_t smem_to_u32(const void* p) {
    uint32_t a;
    asm("{ .reg .u64 t; cvta.to.shared.u64 t, %1; cvt.u32.u64 %0, t; }"
        : "=r"(a) : "l"(p));
    return a;
}
__device__ __forceinline__ void cp_async16(uint32_t dst, const void* src) {
    asm volatile("cp.async.cg.shared.global [%0], [%1], 16;"
                 :: "r"(dst), "l"(src) : "memory");
}
__device__ __forceinline__ void cp_commit() {
    asm volatile("cp.async.commit_group;" ::: "memory");
}
template <int N>
__device__ __forceinline__ void cp_wait() {
    asm volatile("cp.async.wait_group %0;" :: "n"(N) : "memory");
}
__device__ __forceinline__ void ldm_x4(uint32_t (&r)[4], uint32_t addr) {
    asm volatile("ldmatrix.sync.aligned.m8n8.x4.shared.b16 {%0,%1,%2,%3}, [%4];"
                 : "=r"(r[0]), "=r"(r[1]), "=r"(r[2]), "=r"(r[3]) : "r"(addr));
}
__device__ __forceinline__ void mma_f16(float (&d)[4], const uint32_t (&a)[4],
                                        uint32_t b0, uint32_t b1) {
    asm volatile("mma.sync.aligned.m16n8k16.row.col.f32.f16.f16.f32 "
                 "{%0,%1,%2,%3}, {%4,%5,%6,%7}, {%8,%9}, {%0,%1,%2,%3};"
                 : "+f"(d[0]), "+f"(d[1]), "+f"(d[2]), "+f"(d[3])
                 : "r"(a[0]), "r"(a[1]), "r"(a[2]), "r"(a[3]), "r"(b0), "r"(b1));
}

__device__ __forceinline__ void split2f(float x, f16& h, f16& l) {
    h = __float2half_rn(x);
    l = __float2half_rn(x - __half2float(h));
}
__device__ __forceinline__ uint32_t pack_f16x2(float x, float y) {
    __half2 H = __floats2half2_rn(x, y);
    return *reinterpret_cast<uint32_t*>(&H);
}

// ---------------- common tiling constants ----------------
#define KCH 32
#define ROW_BYTES 80
#define TILE_BYTES (128 * ROW_BYTES)        // 10240

__device__ __forceinline__ void load_tile_async(uint32_t smbase, const void* g,
                                                int ld, int k0, int tid) {
    const char* gp = (const char*)g + (size_t)k0 * 2;
    #pragma unroll
    for (int j = 0; j < 2; j++) {
        int i = tid + j * 256;
        int row = i >> 2;
        int c = i & 3;
        cp_async16(smbase + row * ROW_BYTES + c * 16,
                   gp + (size_t)row * ld * 2 + c * 16);
    }
}

// =========================================================================
// f16 2-term GEMM (QKV + out-proj): A split 2xf16, B single f16.
// 256 threads, 8 warps arranged 2(m) x 4(n): warp tile 64x32.
// LDSM bytes/MAC cut 38% vs 32x64 (A frags reused over 2 n-groups,
// B frags over 4 m-tiles). 3-stage cp.async pipeline.
// =========================================================================
#define F16_STAGE (3 * TILE_BYTES)          // 30720
#define F16_SMEM (3 * F16_STAGE)            // 92160

__global__ __launch_bounds__(256)
void k_gemm_nt_f16(const f16* __restrict__ AhG, const f16* __restrict__ AlG,
                   const f16* __restrict__ BfG, const float* __restrict__ biasG,
                   float* __restrict__ OutG)
{
    size_t bm = (size_t)blockIdx.y * 128;
    size_t bn = (size_t)blockIdx.x * 128;
    const f16* Ah = AhG + bm * NC;
    const f16* Al = AlG + bm * NC;
    const f16* Bf = BfG + bn * NC;
    const float* bias = biasG + bn;
    float* Out = OutG + bm * NC + bn;

    extern __shared__ char sm[];
    uint32_t sb = smem_to_u32(sm);
    const int tid = threadIdx.x;             // 256 threads = 8 warps
    const int lane = tid & 31;
    const int warp = tid >> 5;
    const int wm = warp >> 2;                // 0..1  rows: wm*64
    const int wn = warp & 3;                 // 0..3  cols: wn*32

    float acc[4][4][4];                      // [mt][nt][frag]
    #pragma unroll
    for (int mt = 0; mt < 4; mt++)
        #pragma unroll
        for (int nt = 0; nt < 4; nt++)
            #pragma unroll
            for (int j = 0; j < 4; j++) acc[mt][nt][j] = 0.0f;

    const int nch = NC / KCH;

    auto load_chunk = [&](int ch, int s) {
        uint32_t base = sb + s * F16_STAGE;
        int k0 = ch * KCH;
        load_tile_async(base,                  Ah, NC, k0, tid);
        load_tile_async(base + TILE_BYTES,     Al, NC, k0, tid);
        load_tile_async(base + 2 * TILE_BYTES, Bf, NC, k0, tid);
    };

    load_chunk(0, 0);
    cp_commit();
    load_chunk(1, 1);
    cp_commit();

    int stage = 0;
    for (int ch = 0; ch < nch; ch++) {
        if (ch + 1 < nch) cp_wait<1>(); else cp_wait<0>();
        __syncthreads();
        if (ch + 2 < nch) {
            int ns = stage + 2;
            if (ns >= 3) ns -= 3;
            load_chunk(ch + 2, ns);
            cp_commit();
        }

        uint32_t base = sb + stage * F16_STAGE;
        if (++stage == 3) stage = 0;

        #pragma unroll
        for (int ks = 0; ks < 2; ks++) {
            uint32_t koff = (uint32_t)(ks * 32 + (lane >> 4) * 16);
            uint32_t ah[4][4], al[4][4];
            #pragma unroll
            for (int mt = 0; mt < 4; mt++) {
                uint32_t r = wm * 64 + mt * 16 + (lane & 15);
                uint32_t addr = base + r * ROW_BYTES + koff;
                ldm_x4(ah[mt], addr);
                ldm_x4(al[mt], addr + TILE_BYTES);
            }
            uint32_t bfr[2][4];
            #pragma unroll
            for (int ng = 0; ng < 2; ng++) {
                uint32_t r = wn * 32 + ng * 16 + (lane & 15);
                ldm_x4(bfr[ng], base + 2 * TILE_BYTES + r * ROW_BYTES + koff);
            }
            #pragma unroll
            for (int mt = 0; mt < 4; mt++)
                #pragma unroll
                for (int ng = 0; ng < 2; ng++) {
                    mma_f16(acc[mt][2 * ng],     ah[mt], bfr[ng][0], bfr[ng][2]);
                    mma_f16(acc[mt][2 * ng],     al[mt], bfr[ng][0], bfr[ng][2]);
                    mma_f16(acc[mt][2 * ng + 1], ah[mt], bfr[ng][1], bfr[ng][3]);
                    mma_f16(acc[mt][2 * ng + 1], al[mt], bfr[ng][1], bfr[ng][3]);
                }
        }
    }

    #pragma unroll
    for (int mt = 0; mt < 4; mt++) {
        int r0 = wm * 64 + mt * 16 + (lane >> 2);
        #pragma unroll
        for (int nt = 0; nt < 4; nt++) {
            int c = wn * 32 + nt * 8 + (lane & 3) * 2;
            float bx = bias[c], by = bias[c + 1];
            float2 v0 = { acc[mt][nt][0] + bx, acc[mt][nt][1] + by };
            float2 v1 = { acc[mt][nt][2] + bx, acc[mt][nt][3] + by };
            *(float2*)(Out + (size_t)r0 * NC + c) = v0;
            *(float2*)(Out + (size_t)(r0 + 8) * NC + c) = v1;
        }
    }
}

// =========================================================================
// Flash attention: scores (f16 2-term) + online softmax + PV (f16 1-term)
// Double-buffered K AND V (unchanged from R11).
// =========================================================================
#define FT_ROWB 272                          // 256B row + 16B pad
#define FT_TILE (128 * FT_ROWB)              // 34816
#define OFF_K 0
#define OFF_V (2 * FT_TILE)
#define FLASH_SMEM (4 * FT_TILE)             // 139264

__device__ __forceinline__ void fa_load_one(uint32_t dst, const f16* g,
                                            size_t rowbase, size_t ldrow, int tid)
{
    #pragma unroll
    for (int i = 0; i < 8; i++) {
        int idx = tid + i * 256;
        int row = idx >> 4;
        int ch = idx & 15;
        cp_async16(dst + row * FT_ROWB + ch * 16,
                   (const char*)(g + rowbase + (size_t)row * ldrow) + ch * 16);
    }
}

__global__ void __launch_bounds__(256, 1) k_flash()
{
    extern __shared__ char sm[];
    uint32_t sb = smem_to_u32(sm);
    const int tid = threadIdx.x;
    const int lane = tid & 31;
    const int warp = tid >> 5;
    const int q0 = blockIdx.x * 128;
    const int bh = blockIdx.y, b = bh >> 4, h = bh & 15;

    const size_t kbase = (size_t)(b * NS) * NC + (size_t)h * ND;
    const size_t vbase = ((size_t)b * NC + (size_t)h * ND) * NS;

    // ---- stage Q hi/lo through buffers K0/V0; K0&V0 data go to buffer 1 ----
    size_t qbase = (size_t)(b * NS + q0) * NC + (size_t)h * ND;
    fa_load_one(sb + OFF_K, g_qhf, qbase, NC, tid);
    fa_load_one(sb + OFF_V, g_qlf, qbase, NC, tid);
    cp_commit();                                        // group: Q
    fa_load_one(sb + OFF_K + FT_TILE, g_kf, kbase, NC, tid);
    fa_load_one(sb + OFF_V + FT_TILE, g_vtf, vbase, NS, tid);
    cp_commit();                                        // group: K0,V0
    cp_wait<1>();                                       // Q ready
    __syncthreads();

    uint32_t qhf[8][4], qlf[8][4];
    {
        uint32_t rbase = sb + (warp * 16 + (lane & 15)) * FT_ROWB + ((lane >> 4) << 4);
        #pragma unroll
        for (int ks = 0; ks < 8; ks++) {
            ldm_x4(qhf[ks], rbase + OFF_K + ks * 32);
            ldm_x4(qlf[ks], rbase + OFF_V + ks * 32);
        }
    }
    __syncthreads();                                    // Q buffers free

    fa_load_one(sb + OFF_K, g_kf, kbase + (size_t)128 * NC, NC, tid);
    fa_load_one(sb + OFF_V, g_vtf, vbase + 128, NS, tid);
    cp_commit();                                        // group: K1,V1

    float o[16][4];
    #pragma unroll
    for (int i = 0; i < 16; i++) { o[i][0] = 0.f; o[i][1] = 0.f; o[i][2] = 0.f; o[i][3] = 0.f; }
    float m0 = -1e30f, m1 = -1e30f, l0 = 0.f, l1 = 0.f;

    for (int j = 0; j < 16; j++) {
        // groups pending: {KV_j, KV_{j+1}} -> wait for KV_j
        if (j + 1 < 16) cp_wait<1>(); else cp_wait<0>();
        __syncthreads();

        uint32_t bufo = (uint32_t)((j + 1) & 1) * FT_TILE;

        // (B) S = Q @ K_j^T  (f16 2-term)
        float s[16][4];
        #pragma unroll
        for (int i = 0; i < 16; i++) { s[i][0] = 0.f; s[i][1] = 0.f; s[i][2] = 0.f; s[i][3] = 0.f; }
        #pragma unroll
        for (int ng = 0; ng < 8; ng++) {
            #pragma unroll
            for (int ks = 0; ks < 8; ks++) {
                uint32_t addr = sb + OFF_K + bufo + (ng * 16 + (lane & 15)) * FT_ROWB
                              + ((lane >> 4) << 4) + ks * 32;
                uint32_t kf4[4];
                ldm_x4(kf4, addr);
                mma_f16(s[2 * ng],     qhf[ks], kf4[0], kf4[2]);
                mma_f16(s[2 * ng],     qlf[ks], kf4[0], kf4[2]);
                mma_f16(s[2 * ng + 1], qhf[ks], kf4[1], kf4[3]);
                mma_f16(s[2 * ng + 1], qlf[ks], kf4[1], kf4[3]);
            }
        }

        // (D) online softmax: p = exp((s - m)*scale) <= 1 (f16-safe by construction)
        float mx0 = -1e30f, mx1 = -1e30f;
        #pragma unroll
        for (int i = 0; i < 16; i++) {
            mx0 = fmaxf(mx0, fmaxf(s[i][0], s[i][1]));
            mx1 = fmaxf(mx1, fmaxf(s[i][2], s[i][3]));
        }
        mx0 = fmaxf(mx0, __shfl_xor_sync(0xffffffffu, mx0, 1));
        mx0 = fmaxf(mx0, __shfl_xor_sync(0xffffffffu, mx0, 2));
        mx1 = fmaxf(mx1, __shfl_xor_sync(0xffffffffu, mx1, 1));
        mx1 = fmaxf(mx1, __shfl_xor_sync(0xffffffffu, mx1, 2));
        float nm0 = fmaxf(m0, mx0), nm1 = fmaxf(m1, mx1);
        float a0 = __expf((m0 - nm0) * SM_SCALE);
        float a1 = __expf((m1 - nm1) * SM_SCALE);
        m0 = nm0; m1 = nm1;
        float ps0 = 0.f, ps1 = 0.f;
        #pragma unroll
        for (int i = 0; i < 16; i++) {
            s[i][0] = __expf((s[i][0] - m0) * SM_SCALE);
            s[i][1] = __expf((s[i][1] - m0) * SM_SCALE);
            s[i][2] = __expf((s[i][2] - m1) * SM_SCALE);
            s[i][3] = __expf((s[i][3] - m1) * SM_SCALE);
            ps0 += s[i][0] + s[i][1];
            ps1 += s[i][2] + s[i][3];
        }
        l0 = l0 * a0 + ps0;
        l1 = l1 * a1 + ps1;
        #pragma unroll
        for (int i = 0; i < 16; i++) {
            o[i][0] *= a0; o[i][1] *= a0; o[i][2] *= a1; o[i][3] *= a1;
        }

        // (F) ctx += P @ V_j  (P single f16 in [0,1], V single f16)
        #pragma unroll
        for (int ks = 0; ks < 8; ks++) {
            uint32_t pa[4];
            pa[0] = pack_f16x2(s[2 * ks][0],     s[2 * ks][1]);
            pa[1] = pack_f16x2(s[2 * ks][2],     s[2 * ks][3]);
            pa[2] = pack_f16x2(s[2 * ks + 1][0], s[2 * ks + 1][1]);
            pa[3] = pack_f16x2(s[2 * ks + 1][2], s[2 * ks + 1][3]);
            #pragma unroll
            for (int ng = 0; ng < 8; ng++) {
                uint32_t addr = sb + OFF_V + bufo + (ng * 16 + (lane & 15)) * FT_ROWB
                              + ((lane >> 4) << 4) + ks * 32;
                uint32_t vf4[4];
                ldm_x4(vf4, addr);
                mma_f16(o[2 * ng],     pa, vf4[0], vf4[2]);
                mma_f16(o[2 * ng + 1], pa, vf4[1], vf4[3]);
            }
        }

        // (G) buffers for iter j are free -> start K_{j+2}, V_{j+2} into them
        __syncthreads();
        if (j + 2 < 16) {
            fa_load_one(sb + OFF_K + bufo, g_kf,
                        kbase + (size_t)(j + 2) * 128 * NC, NC, tid);
            fa_load_one(sb + OFF_V + bufo, g_vtf,
                        vbase + (size_t)(j + 2) * 128, NS, tid);
            cp_commit();
        }
    }

    // ---- finalize: normalize, split to f16 hi/lo, write ctx ----
    l0 += __shfl_xor_sync(0xffffffffu, l0, 1);
    l0 += __shfl_xor_sync(0xffffffffu, l0, 2);
    l1 += __shfl_xor_sync(0xffffffffu, l1, 1);
    l1 += __shfl_xor_sync(0xffffffffu, l1, 2);
    float i0 = 1.0f / l0, i1 = 1.0f / l1;

    size_t gr0 = (size_t)(b * NS + q0 + warp * 16 + (lane >> 2));
    #pragma unroll
    for (int nt = 0; nt < 16; nt++) {
        int c = h * ND + nt * 8 + (lane & 3) * 2;
        f16 h0, h1, lo0, lo1;
        split2f(o[nt][0] * i0, h0, lo0);
        split2f(o[nt][1] * i0, h1, lo1);
        *(__half2*)(g_chf + gr0 * NC + c) = __half2{h0, h1};
        *(__half2*)(g_clf + gr0 * NC + c) = __half2{lo0, lo1};
        split2f(o[nt][2] * i1, h0, lo0);
        split2f(o[nt][3] * i1, h1, lo1);
        *(__half2*)(g_chf + (gr0 + 8) * NC + c) = __half2{h0, h1};
        *(__half2*)(g_clf + (gr0 + 8) * NC + c) = __half2{lo0, lo1};
    }
}

// ---------------- elementwise kernels ----------------
__global__ __launch_bounds__(256) void cvt_split_f16(const float* __restrict__ src,
                                                     f16* __restrict__ hi,
                                                     f16* __restrict__ lo)
{
    size_t i = (size_t)blockIdx.x * 256 + threadIdx.x;
    float4 v = ((const float4*)src)[i];
    f16 h0, h1, h2, h3, l0, l1, l2, l3;
    split2f(v.x, h0, l0); split2f(v.y, h1, l1);
    split2f(v.z, h2, l2); split2f(v.w, h3, l3);
    __half2* hp = (__half2*)hi;
    __half2* lp = (__half2*)lo;
    hp[2 * i]     = __half2{h0, h1};
    hp[2 * i + 1] = __half2{h2, h3};
    lp[2 * i]     = __half2{l0, l1};
    lp[2 * i + 1] = __half2{l2, l3};
}

// Convert the 4 weight matrices in one launch: blockIdx.y selects tensor.
__global__ __launch_bounds__(256) void cvt_f16_w(
    const float* __restrict__ s0, const float* __restrict__ s1,
    const float* __restrict__ s2, const float* __restrict__ s3,
    f16* __restrict__ d0, f16* __restrict__ d1,
    f16* __restrict__ d2, f16* __restrict__ d3)
{
    const float* src = (blockIdx.y == 0) ? s0 : (blockIdx.y == 1) ? s1
                     : (blockIdx.y == 2) ? s2 : s3;
    f16* dst = (blockIdx.y == 0) ? d0 : (blockIdx.y == 1) ? d1
             : (blockIdx.y == 2) ? d2 : d3;
    size_t i = (size_t)blockIdx.x * 256 + threadIdx.x;
    float4 v = ((const float4*)src)[i];
    __half2* dp = (__half2*)dst;
    dp[2 * i]     = __floats2half2_rn(v.x, v.y);
    dp[2 * i + 1] = __floats2half2_rn(v.z, v.w);
}

// V transpose to single f16: g_v[(b*S+s), c] -> vT[(b*C+c), s]
__global__ __launch_bounds__(256) void transpose_v_f16()
{
    __shared__ float t[32][33];
    int b = blockIdx.z;
    int s0 = blockIdx.x * 32, c0 = blockIdx.y * 32;
    int tx = threadIdx.x, ty = threadIdx.y;  // 32 x 8
    #pragma unroll
    for (int j = 0; j < 4; j++) {
        int s = s0 + ty + j * 8;
        t[ty + j * 8][tx] = g_v[((size_t)b * NS + s) * NC + c0 + tx];
    }
    __syncthreads();
    #pragma unroll
    for (int j = 0; j < 4; j++) {
        int c = c0 + ty + j * 8;
        g_vtf[((size_t)b * NC + c) * NS + s0 + tx] = __float2half_rn(t[tx][ty + j * 8]);
    }
}

// Per-head RMSNorm + RoPE; reads fp32 g_q/g_k; writes Q split 2xf16, K single f16.
__global__ __launch_bounds__(256) void rmsnorm_rope(
    const float* __restrict__ rope,
    const float* __restrict__ gq, const float* __restrict__ gk)
{
    int warp = blockIdx.x * 8 + (threadIdx.x >> 5);
    int lane = threadIdx.x & 31;
    int m = warp >> 4;
    int h = warp & 15;
    int s = m & (NS - 1);

    size_t off = (size_t)m * NC + h * ND;
    const float* qr = g_q + off;
    const float* kr = g_k + off;
    const float* rp = rope + (size_t)s * (ND / 2) * 4;
    int d = lane * 4;

    float4 xq = *(const float4*)(qr + d);
    float4 xk = *(const float4*)(kr + d);
    float ssq = xq.x * xq.x + xq.y * xq.y + xq.z * xq.z + xq.w * xq.w;
    float ssk = xk.x * xk.x + xk.y * xk.y + xk.z * xk.z + xk.w * xk.w;
    #pragma unroll
    for (int o = 16; o; o >>= 1) {
        ssq += __shfl_xor_sync(0xffffffffu, ssq, o);
        ssk += __shfl_xor_sync(0xffffffffu, ssk, o);
    }
    float rq = rsqrtf(ssq * (1.0f / ND) + RMS_EPS);
    float rk = rsqrtf(ssk * (1.0f / ND) + RMS_EPS);

    float4 gqv = *(const float4*)(gq + d);
    float4 gkv = *(const float4*)(gk + d);
    xq.x *= rq * gqv.x; xq.y *= rq * gqv.y; xq.z *= rq * gqv.z; xq.w *= rq * gqv.w;
    xk.x *= rk * gkv.x; xk.y *= rk * gkv.y; xk.z *= rk * gkv.z; xk.w *= rk * gkv.w;

    float4 r0 = *(const float4*)(rp + (size_t)(2 * lane) * 4);
    float4 r1 = *(const float4*)(rp + (size_t)(2 * lane + 1) * 4);
    float4 oq, ok;
    oq.x = r0.x * xq.x + r0.y * xq.y;  oq.y = r0.z * xq.x + r0.w * xq.y;
    oq.z = r1.x * xq.z + r1.y * xq.w;  oq.w = r1.z * xq.z + r1.w * xq.w;
    ok.x = r0.x * xk.x + r0.y * xk.y;  ok.y = r0.z * xk.x + r0.w * xk.y;
    ok.z = r1.x * xk.z + r1.y * xk.w;  ok.w = r1.z * xk.z + r1.w * xk.w;

    f16 h0, h1, h2, h3, l0, l1, l2, l3;
    split2f(oq.x, h0, l0); split2f(oq.y, h1, l1);
    split2f(oq.z, h2, l2); split2f(oq.w, h3, l3);
    *(__half2*)(g_qhf + off + d)     = __half2{h0, h1};
    *(__half2*)(g_qhf + off + d + 2) = __half2{h2, h3};
    *(__half2*)(g_qlf + off + d)     = __half2{l0, l1};
    *(__half2*)(g_qlf + off + d + 2) = __half2{l2, l3};

    *(__half2*)(g_kf + off + d)     = __floats2half2_rn(ok.x, ok.y);
    *(__half2*)(g_kf + off + d + 2) = __floats2half2_rn(ok.z, ok.w);
}

// ---------------- launch ----------------
extern "C" void kernel_launch(void* const* d_in, const int* in_sizes, int n_in,
                              void* d_out, int out_size)
{
    const float* x    = (const float*)d_in[0];
    const float* rope = (const float*)d_in[1];
    const float* Wq   = (const float*)d_in[2];
    const float* bq   = (const float*)d_in[3];
    const float* Wk   = (const float*)d_in[4];
    const float* bk   = (const float*)d_in[5];
    const float* Wv   = (const float*)d_in[6];
    const float* bv   = (const float*)d_in[7];
    const float* gq   = (const float*)d_in[8];
    const float* gk   = (const float*)d_in[9];
    const float* Wo   = (const float*)d_in[10];
    const float* bo   = (const float*)d_in[11];
    float* out = (float*)d_out;

    cudaFuncSetAttribute(k_gemm_nt_f16, cudaFuncAttributeMaxDynamicSharedMemorySize, F16_SMEM);
    cudaFuncSetAttribute(k_flash, cudaFuncAttributeMaxDynamicSharedMemorySize, FLASH_SMEM);

    float *qp, *kp, *vp;
    f16 *xhf, *xlf, *wqf, *wkf, *wvf, *wof, *chf, *clf;
    cudaGetSymbolAddress((void**)&qp, g_q);
    cudaGetSymbolAddress((void**)&kp, g_k);
    cudaGetSymbolAddress((void**)&vp, g_v);
    cudaGetSymbolAddress((void**)&xhf, g_xhf); cudaGetSymbolAddress((void**)&xlf, g_xlf);
    cudaGetSymbolAddress((void**)&wqf, g_wqf); cudaGetSymbolAddress((void**)&wkf, g_wkf);
    cudaGetSymbolAddress((void**)&wvf, g_wvf); cudaGetSymbolAddress((void**)&wof, g_wof);
    cudaGetSymbolAddress((void**)&chf, g_chf); cudaGetSymbolAddress((void**)&clf, g_clf);

    const size_t nX = (size_t)NM * NC;       // 8M elems
    const size_t nW = (size_t)NC * NC;       // 4M elems

    cvt_split_f16<<<(unsigned)(nX / 1024), 256>>>(x, xhf, xlf);
    cvt_f16_w<<<dim3((unsigned)(nW / 1024), 4), 256>>>(Wq, Wk, Wv, Wo,
                                                       wqf, wkf, wvf, wof);

    dim3 gProj(NC / 128, NM / 128);          // (16, 32)
    k_gemm_nt_f16<<<gProj, 256, F16_SMEM>>>(xhf, xlf, wqf, bq, qp);
    k_gemm_nt_f16<<<gProj, 256, F16_SMEM>>>(xhf, xlf, wkf, bk, kp);
    k_gemm_nt_f16<<<gProj, 256, F16_SMEM>>>(xhf, xlf, wvf, bv, vp);

    rmsnorm_rope<<<(NM * NH) / 8, 256>>>(rope, gq, gk);
    transpose_v_f16<<<dim3(NS / 32, NC / 32, NB), dim3(32, 8)>>>();

    k_flash<<<dim3(NS / 128, NBH), 256, FLASH_SMEM>>>();

    k_gemm_nt_f16<<<gProj, 256, F16_SMEM>>>(chf, clf, wof, bo, out);
}

// round 14
// speedup vs baseline: 1.0906x; 1.0373x over previous
#include <cuda_runtime.h>
#include <cuda_bf16.h>
#include <cuda_fp16.h>
#include <math.h>
#include <stdint.h>
#include <stddef.h>

#define NB 2
#define NS 2048
#define NC 2048
#define ND 128
#define NH 16
#define NM (NB * NS)       // 4096
#define NBH (NB * NH)      // 32
#define RMS_EPS 1.1920928955078125e-07f
#define SM_SCALE 0.08838834764831844f

typedef __half f16;

// ---------------- scratch (device globals; no allocation) ----------------
__device__ float g_v[(size_t)NM * NC];

// f16 operands
__device__ f16 g_xhf[(size_t)NM * NC], g_xlf[(size_t)NM * NC];
__device__ f16 g_wqf[(size_t)NC * NC], g_wkf[(size_t)NC * NC];
__device__ f16 g_wvf[(size_t)NC * NC], g_wof[(size_t)NC * NC];
__device__ f16 g_vtf[(size_t)NB * NC * NS];
__device__ f16 g_chf[(size_t)NM * NC], g_clf[(size_t)NM * NC];
__device__ f16 g_qhf[(size_t)NM * NC], g_qlf[(size_t)NM * NC];   // Q split 2xf16
__device__ f16 g_kf[(size_t)NM * NC];                            // K single f16

// ---------------- PTX helpers (sm_80-era, family-target safe) -------------
__device__ __forceinline__ uint32_t smem_to_u32(const void* p) {
    uint32_t a;
    asm("{ .reg .u64 t; cvta.to.shared.u64 t, %1; cvt.u32.u64 %0, t; }"
        : "=r"(a) : "l"(p));
    return a;
}
__device__ __forceinline__ void cp_async16(uint32_t dst, const void* src) {
    asm volatile("cp.async.cg.shared.global [%0], [%1], 16;"
                 :: "r"(dst), "l"(src) : "memory");
}
__device__ __forceinline__ void cp_commit() {
    asm volatile("cp.async.commit_group;" ::: "memory");
}
template <int N>
__device__ __forceinline__ void cp_wait() {
    asm volatile("cp.async.wait_group %0;" :: "n"(N) : "memory");
}
__device__ __forceinline__ void ldm_x4(uint32_t (&r)[4], uint32_t addr) {
    asm volatile("ldmatrix.sync.aligned.m8n8.x4.shared.b16 {%0,%1,%2,%3}, [%4];"
                 : "=r"(r[0]), "=r"(r[1]), "=r"(r[2]), "=r"(r[3]) : "r"(addr));
}
__device__ __forceinline__ void mma_f16(float (&d)[4], const uint32_t (&a)[4],
                                        uint32_t b0, uint32_t b1) {
    asm volatile("mma.sync.aligned.m16n8k16.row.col.f32.f16.f16.f32 "
                 "{%0,%1,%2,%3}, {%4,%5,%6,%7}, {%8,%9}, {%0,%1,%2,%3};"
                 : "+f"(d[0]), "+f"(d[1]), "+f"(d[2]), "+f"(d[3])
                 : "r"(a[0]), "r"(a[1]), "r"(a[2]), "r"(a[3]), "r"(b0), "r"(b1));
}

__device__ __forceinline__ void split2f(float x, f16& h, f16& l) {
    h = __float2half_rn(x);
    l = __float2half_rn(x - __half2float(h));
}
__device__ __forceinline__ uint32_t pack_f16x2(float x, float y) {
    __half2 H = __floats2half2_rn(x, y);
    return *reinterpret_cast<uint32_t*>(&H);
}

// ---------------- common tiling constants ----------------
#define KCH 32
#define ROW_BYTES 80
#define TILE_BYTES (128 * ROW_BYTES)        // 10240

__device__ __forceinline__ void load_tile_async(uint32_t smbase, const void* g,
                                                int ld, int k0, int tid) {
    const char* gp = (const char*)g + (size_t)k0 * 2;
    #pragma unroll
    for (int j = 0; j < 2; j++) {
        int i = tid + j * 256;
        int row = i >> 2;
        int c = i & 3;
        cp_async16(smbase + row * ROW_BYTES + c * 16,
                   gp + (size_t)row * ld * 2 + c * 16);
    }
}

// =========================================================================
// f16 2-term GEMM: A split 2xf16, B single f16. R11 tiling (32x64 warp
// tile, 8 warps, 3-stage pipeline) — the measured-best config.
// MODE 0: fp32 out + bias (V proj, out-proj)
// MODE 1: fused bias + per-head RMSNorm + RoPE -> split f16 (Q)
// MODE 2: fused bias + per-head RMSNorm + RoPE -> single f16 (K)
// =========================================================================
#define F16_STAGE (3 * TILE_BYTES)          // 30720
#define F16_SMEM (3 * F16_STAGE)            // 92160

template <int MODE>
__global__ __launch_bounds__(256)
void k_gemm_f16(const f16* __restrict__ AhG, const f16* __restrict__ AlG,
                const f16* __restrict__ BfG, const float* __restrict__ biasG,
                float* __restrict__ OutFG,
                f16* __restrict__ OutHG, f16* __restrict__ OutLG,
                const float* __restrict__ rope, const float* __restrict__ gamma)
{
    size_t bm = (size_t)blockIdx.y * 128;
    size_t bn = (size_t)blockIdx.x * 128;
    const f16* Ah = AhG + bm * NC;
    const f16* Al = AlG + bm * NC;
    const f16* Bf = BfG + bn * NC;
    const float* bias = biasG + bn;

    extern __shared__ char sm[];
    uint32_t sb = smem_to_u32(sm);
    const int tid = threadIdx.x;             // 256 threads = 8 warps
    const int lane = tid & 31;
    const int warp = tid >> 5;
    const int wm = warp >> 1;                // 0..3  rows: wm*32
    const int wn = warp & 1;                 // 0..1  cols: wn*64

    float acc[2][8][4];
    #pragma unroll
    for (int mt = 0; mt < 2; mt++)
        #pragma unroll
        for (int nt = 0; nt < 8; nt++)
            #pragma unroll
            for (int j = 0; j < 4; j++) acc[mt][nt][j] = 0.0f;

    const int nch = NC / KCH;

    auto load_chunk = [&](int ch, int s) {
        uint32_t base = sb + s * F16_STAGE;
        int k0 = ch * KCH;
        load_tile_async(base,                  Ah, NC, k0, tid);
        load_tile_async(base + TILE_BYTES,     Al, NC, k0, tid);
        load_tile_async(base + 2 * TILE_BYTES, Bf, NC, k0, tid);
    };

    load_chunk(0, 0);
    cp_commit();
    load_chunk(1, 1);
    cp_commit();

    int stage = 0;
    for (int ch = 0; ch < nch; ch++) {
        if (ch + 1 < nch) cp_wait<1>(); else cp_wait<0>();
        __syncthreads();
        if (ch + 2 < nch) {
            int ns = stage + 2;
            if (ns >= 3) ns -= 3;
            load_chunk(ch + 2, ns);
            cp_commit();
        }

        uint32_t base = sb + stage * F16_STAGE;
        if (++stage == 3) stage = 0;

        #pragma unroll
        for (int ks = 0; ks < 2; ks++) {
            uint32_t koff = (uint32_t)(ks * 32 + (lane >> 4) * 16);
            uint32_t ah[2][4], al[2][4];
            #pragma unroll
            for (int mt = 0; mt < 2; mt++) {
                uint32_t r = wm * 32 + mt * 16 + (lane & 15);
                uint32_t addr = base + r * ROW_BYTES + koff;
                ldm_x4(ah[mt], addr);
                ldm_x4(al[mt], addr + TILE_BYTES);
            }
            uint32_t bfr[4][4];
            #pragma unroll
            for (int ng = 0; ng < 4; ng++) {
                uint32_t r = wn * 64 + ng * 16 + (lane & 15);
                ldm_x4(bfr[ng], base + 2 * TILE_BYTES + r * ROW_BYTES + koff);
            }
            #pragma unroll
            for (int mt = 0; mt < 2; mt++)
                #pragma unroll
                for (int ng = 0; ng < 4; ng++) {
                    mma_f16(acc[mt][2 * ng],     ah[mt], bfr[ng][0], bfr[ng][2]);
                    mma_f16(acc[mt][2 * ng],     al[mt], bfr[ng][0], bfr[ng][2]);
                    mma_f16(acc[mt][2 * ng + 1], ah[mt], bfr[ng][1], bfr[ng][3]);
                    mma_f16(acc[mt][2 * ng + 1], al[mt], bfr[ng][1], bfr[ng][3]);
                }
        }
    }

    // fold bias into acc (same single-add as before)
    #pragma unroll
    for (int mt = 0; mt < 2; mt++)
        #pragma unroll
        for (int nt = 0; nt < 8; nt++) {
            int c = wn * 64 + nt * 8 + (lane & 3) * 2;
            float bx = bias[c], by = bias[c + 1];
            acc[mt][nt][0] += bx; acc[mt][nt][1] += by;
            acc[mt][nt][2] += bx; acc[mt][nt][3] += by;
        }

    if (MODE == 0) {
        float* Out = OutFG + bm * NC + bn;
        #pragma unroll
        for (int mt = 0; mt < 2; mt++) {
            int r0 = wm * 32 + mt * 16 + (lane >> 2);
            #pragma unroll
            for (int nt = 0; nt < 8; nt++) {
                int c = wn * 64 + nt * 8 + (lane & 3) * 2;
                float2 v0 = { acc[mt][nt][0], acc[mt][nt][1] };
                float2 v1 = { acc[mt][nt][2], acc[mt][nt][3] };
                *(float2*)(Out + (size_t)r0 * NC + c) = v0;
                *(float2*)(Out + (size_t)(r0 + 8) * NC + c) = v1;
            }
        }
    } else {
        // fused per-head RMSNorm + RoPE (tile == one head)
        __syncthreads();                     // pipeline smem reads done
        float* sums = (float*)sm;            // [2][128]
        #pragma unroll
        for (int mt = 0; mt < 2; mt++) {
            float ss0 = 0.f, ss1 = 0.f;
            #pragma unroll
            for (int nt = 0; nt < 8; nt++) {
                ss0 += acc[mt][nt][0] * acc[mt][nt][0]
                     + acc[mt][nt][1] * acc[mt][nt][1];
                ss1 += acc[mt][nt][2] * acc[mt][nt][2]
                     + acc[mt][nt][3] * acc[mt][nt][3];
            }
            ss0 += __shfl_xor_sync(0xffffffffu, ss0, 1);
            ss0 += __shfl_xor_sync(0xffffffffu, ss0, 2);
            ss1 += __shfl_xor_sync(0xffffffffu, ss1, 1);
            ss1 += __shfl_xor_sync(0xffffffffu, ss1, 2);
            int r0 = wm * 32 + mt * 16 + (lane >> 2);
            if ((lane & 3) == 0) {
                sums[wn * 128 + r0] = ss0;
                sums[wn * 128 + r0 + 8] = ss1;
            }
        }
        __syncthreads();
        #pragma unroll
        for (int mt = 0; mt < 2; mt++) {
            int r0 = wm * 32 + mt * 16 + (lane >> 2);
            int m0 = (int)bm + r0, m1 = m0 + 8;
            int s0 = m0 & (NS - 1), s1 = m1 & (NS - 1);
            float rq0 = rsqrtf((sums[r0] + sums[128 + r0]) * (1.0f / ND) + RMS_EPS);
            float rq1 = rsqrtf((sums[r0 + 8] + sums[128 + r0 + 8]) * (1.0f / ND) + RMS_EPS);
            #pragma unroll
            for (int nt = 0; nt < 8; nt++) {
                int c = wn * 64 + nt * 8 + (lane & 3) * 2;
                float g0 = gamma[c], g1 = gamma[c + 1];
                float4 rp0 = *(const float4*)(rope + (size_t)s0 * 256 + c * 2);
                float4 rp1 = *(const float4*)(rope + (size_t)s1 * 256 + c * 2);
                float x0 = acc[mt][nt][0] * rq0 * g0;
                float x1 = acc[mt][nt][1] * rq0 * g1;
                float y0 = rp0.x * x0 + rp0.y * x1;
                float y1 = rp0.z * x0 + rp0.w * x1;
                float x2 = acc[mt][nt][2] * rq1 * g0;
                float x3 = acc[mt][nt][3] * rq1 * g1;
                float y2 = rp1.x * x2 + rp1.y * x3;
                float y3 = rp1.z * x2 + rp1.w * x3;
                size_t o0 = (size_t)m0 * NC + bn + c;
                size_t o1 = (size_t)m1 * NC + bn + c;
                if (MODE == 1) {
                    f16 h0, l0, h1, l1;
                    split2f(y0, h0, l0); split2f(y1, h1, l1);
                    *(__half2*)(OutHG + o0) = __half2{h0, h1};
                    *(__half2*)(OutLG + o0) = __half2{l0, l1};
                    split2f(y2, h0, l0); split2f(y3, h1, l1);
                    *(__half2*)(OutHG + o1) = __half2{h0, h1};
                    *(__half2*)(OutLG + o1) = __half2{l0, l1};
                } else {
                    *(__half2*)(OutHG + o0) = __floats2half2_rn(y0, y1);
                    *(__half2*)(OutHG + o1) = __floats2half2_rn(y2, y3);
                }
            }
        }
    }
}

// =========================================================================
// Flash attention: scores (f16 2-term) + online softmax + PV (f16 1-term)
// Double-buffered K AND V (unchanged from R11).
// =========================================================================
#define FT_ROWB 272                          // 256B row + 16B pad
#define FT_TILE (128 * FT_ROWB)              // 34816
#define OFF_K 0
#define OFF_V (2 * FT_TILE)
#define FLASH_SMEM (4 * FT_TILE)             // 139264

__device__ __forceinline__ void fa_load_one(uint32_t dst, const f16* g,
                                            size_t rowbase, size_t ldrow, int tid)
{
    #pragma unroll
    for (int i = 0; i < 8; i++) {
        int idx = tid + i * 256;
        int row = idx >> 4;
        int ch = idx & 15;
        cp_async16(dst + row * FT_ROWB + ch * 16,
                   (const char*)(g + rowbase + (size_t)row * ldrow) + ch * 16);
    }
}

__global__ void __launch_bounds__(256, 1) k_flash()
{
    extern __shared__ char sm[];
    uint32_t sb = smem_to_u32(sm);
    const int tid = threadIdx.x;
    const int lane = tid & 31;
    const int warp = tid >> 5;
    const int q0 = blockIdx.x * 128;
    const int bh = blockIdx.y, b = bh >> 4, h = bh & 15;

    const size_t kbase = (size_t)(b * NS) * NC + (size_t)h * ND;
    const size_t vbase = ((size_t)b * NC + (size_t)h * ND) * NS;

    size_t qbase = (size_t)(b * NS + q0) * NC + (size_t)h * ND;
    fa_load_one(sb + OFF_K, g_qhf, qbase, NC, tid);
    fa_load_one(sb + OFF_V, g_qlf, qbase, NC, tid);
    cp_commit();                                        // group: Q
    fa_load_one(sb + OFF_K + FT_TILE, g_kf, kbase, NC, tid);
    fa_load_one(sb + OFF_V + FT_TILE, g_vtf, vbase, NS, tid);
    cp_commit();                                        // group: K0,V0
    cp_wait<1>();                                       // Q ready
    __syncthreads();

    uint32_t qhf[8][4], qlf[8][4];
    {
        uint32_t rbase = sb + (warp * 16 + (lane & 15)) * FT_ROWB + ((lane >> 4) << 4);
        #pragma unroll
        for (int ks = 0; ks < 8; ks++) {
            ldm_x4(qhf[ks], rbase + OFF_K + ks * 32);
            ldm_x4(qlf[ks], rbase + OFF_V + ks * 32);
        }
    }
    __syncthreads();                                    // Q buffers free

    fa_load_one(sb + OFF_K, g_kf, kbase + (size_t)128 * NC, NC, tid);
    fa_load_one(sb + OFF_V, g_vtf, vbase + 128, NS, tid);
    cp_commit();                                        // group: K1,V1

    float o[16][4];
    #pragma unroll
    for (int i = 0; i < 16; i++) { o[i][0] = 0.f; o[i][1] = 0.f; o[i][2] = 0.f; o[i][3] = 0.f; }
    float m0 = -1e30f, m1 = -1e30f, l0 = 0.f, l1 = 0.f;

    for (int j = 0; j < 16; j++) {
        if (j + 1 < 16) cp_wait<1>(); else cp_wait<0>();
        __syncthreads();

        uint32_t bufo = (uint32_t)((j + 1) & 1) * FT_TILE;

        float s[16][4];
        #pragma unroll
        for (int i = 0; i < 16; i++) { s[i][0] = 0.f; s[i][1] = 0.f; s[i][2] = 0.f; s[i][3] = 0.f; }
        #pragma unroll
        for (int ng = 0; ng < 8; ng++) {
            #pragma unroll
            for (int ks = 0; ks < 8; ks++) {
                uint32_t addr = sb + OFF_K + bufo + (ng * 16 + (lane & 15)) * FT_ROWB
                              + ((lane >> 4) << 4) + ks * 32;
                uint32_t kf4[4];
                ldm_x4(kf4, addr);
                mma_f16(s[2 * ng],     qhf[ks], kf4[0], kf4[2]);
                mma_f16(s[2 * ng],     qlf[ks], kf4[0], kf4[2]);
                mma_f16(s[2 * ng + 1], qhf[ks], kf4[1], kf4[3]);
                mma_f16(s[2 * ng + 1], qlf[ks], kf4[1], kf4[3]);
            }
        }

        float mx0 = -1e30f, mx1 = -1e30f;
        #pragma unroll
        for (int i = 0; i < 16; i++) {
            mx0 = fmaxf(mx0, fmaxf(s[i][0], s[i][1]));
            mx1 = fmaxf(mx1, fmaxf(s[i][2], s[i][3]));
        }
        mx0 = fmaxf(mx0, __shfl_xor_sync(0xffffffffu, mx0, 1));
        mx0 = fmaxf(mx0, __shfl_xor_sync(0xffffffffu, mx0, 2));
        mx1 = fmaxf(mx1, __shfl_xor_sync(0xffffffffu, mx1, 1));
        mx1 = fmaxf(mx1, __shfl_xor_sync(0xffffffffu, mx1, 2));
        float nm0 = fmaxf(m0, mx0), nm1 = fmaxf(m1, mx1);
        float a0 = __expf((m0 - nm0) * SM_SCALE);
        float a1 = __expf((m1 - nm1) * SM_SCALE);
        m0 = nm0; m1 = nm1;
        float ps0 = 0.f, ps1 = 0.f;
        #pragma unroll
        for (int i = 0; i < 16; i++) {
            s[i][0] = __expf((s[i][0] - m0) * SM_SCALE);
            s[i][1] = __expf((s[i][1] - m0) * SM_SCALE);
            s[i][2] = __expf((s[i][2] - m1) * SM_SCALE);
            s[i][3] = __expf((s[i][3] - m1) * SM_SCALE);
            ps0 += s[i][0] + s[i][1];
            ps1 += s[i][2] + s[i][3];
        }
        l0 = l0 * a0 + ps0;
        l1 = l1 * a1 + ps1;
        #pragma unroll
        for (int i = 0; i < 16; i++) {
            o[i][0] *= a0; o[i][1] *= a0; o[i][2] *= a1; o[i][3] *= a1;
        }

        #pragma unroll
        for (int ks = 0; ks < 8; ks++) {
            uint32_t pa[4];
            pa[0] = pack_f16x2(s[2 * ks][0],     s[2 * ks][1]);
            pa[1] = pack_f16x2(s[2 * ks][2],     s[2 * ks][3]);
            pa[2] = pack_f16x2(s[2 * ks + 1][0], s[2 * ks + 1][1]);
            pa[3] = pack_f16x2(s[2 * ks + 1][2], s[2 * ks + 1][3]);
            #pragma unroll
            for (int ng = 0; ng < 8; ng++) {
                uint32_t addr = sb + OFF_V + bufo + (ng * 16 + (lane & 15)) * FT_ROWB
                              + ((lane >> 4) << 4) + ks * 32;
                uint32_t vf4[4];
                ldm_x4(vf4, addr);
                mma_f16(o[2 * ng],     pa, vf4[0], vf4[2]);
                mma_f16(o[2 * ng + 1], pa, vf4[1], vf4[3]);
            }
        }

        __syncthreads();
        if (j + 2 < 16) {
            fa_load_one(sb + OFF_K + bufo, g_kf,
                        kbase + (size_t)(j + 2) * 128 * NC, NC, tid);
            fa_load_one(sb + OFF_V + bufo, g_vtf,
                        vbase + (size_t)(j + 2) * 128, NS, tid);
            cp_commit();
        }
    }

    l0 += __shfl_xor_sync(0xffffffffu, l0, 1);
    l0 += __shfl_xor_sync(0xffffffffu, l0, 2);
    l1 += __shfl_xor_sync(0xffffffffu, l1, 1);
    l1 += __shfl_xor_sync(0xffffffffu, l1, 2);
    float i0 = 1.0f / l0, i1 = 1.0f / l1;

    size_t gr0 = (size_t)(b * NS + q0 + warp * 16 + (lane >> 2));
    #pragma unroll
    for (int nt = 0; nt < 16; nt++) {
        int c = h * ND + nt * 8 + (lane & 3) * 2;
        f16 h0, h1, lo0, lo1;
        split2f(o[nt][0] * i0, h0, lo0);
        split2f(o[nt][1] * i0, h1, lo1);
        *(__half2*)(g_chf + gr0 * NC + c) = __half2{h0, h1};
        *(__half2*)(g_clf + gr0 * NC + c) = __half2{lo0, lo1};
        split2f(o[nt][2] * i1, h0, lo0);
        split2f(o[nt][3] * i1, h1, lo1);
        *(__half2*)(g_chf + (gr0 + 8) * NC + c) = __half2{h0, h1};
        *(__half2*)(g_clf + (gr0 + 8) * NC + c) = __half2{lo0, lo1};
    }
}

// ---------------- elementwise kernels ----------------
__global__ __launch_bounds__(256) void cvt_split_f16(const float* __restrict__ src,
                                                     f16* __restrict__ hi,
                                                     f16* __restrict__ lo)
{
    size_t i = (size_t)blockIdx.x * 256 + threadIdx.x;
    float4 v = ((const float4*)src)[i];
    f16 h0, h1, h2, h3, l0, l1, l2, l3;
    split2f(v.x, h0, l0); split2f(v.y, h1, l1);
    split2f(v.z, h2, l2); split2f(v.w, h3, l3);
    __half2* hp = (__half2*)hi;
    __half2* lp = (__half2*)lo;
    hp[2 * i]     = __half2{h0, h1};
    hp[2 * i + 1] = __half2{h2, h3};
    lp[2 * i]     = __half2{l0, l1};
    lp[2 * i + 1] = __half2{l2, l3};
}

// Convert the 4 weight matrices in one launch: blockIdx.y selects tensor.
__global__ __launch_bounds__(256) void cvt_f16_w(
    const float* __restrict__ s0, const float* __restrict__ s1,
    const float* __restrict__ s2, const float* __restrict__ s3,
    f16* __restrict__ d0, f16* __restrict__ d1,
    f16* __restrict__ d2, f16* __restrict__ d3)
{
    const float* src = (blockIdx.y == 0) ? s0 : (blockIdx.y == 1) ? s1
                     : (blockIdx.y == 2) ? s2 : s3;
    f16* dst = (blockIdx.y == 0) ? d0 : (blockIdx.y == 1) ? d1
             : (blockIdx.y == 2) ? d2 : d3;
    size_t i = (size_t)blockIdx.x * 256 + threadIdx.x;
    float4 v = ((const float4*)src)[i];
    __half2* dp = (__half2*)dst;
    dp[2 * i]     = __floats2half2_rn(v.x, v.y);
    dp[2 * i + 1] = __floats2half2_rn(v.z, v.w);
}

// V transpose to single f16: g_v[(b*S+s), c] -> vT[(b*C+c), s]
__global__ __launch_bounds__(256) void transpose_v_f16()
{
    __shared__ float t[32][33];
    int b = blockIdx.z;
    int s0 = blockIdx.x * 32, c0 = blockIdx.y * 32;
    int tx = threadIdx.x, ty = threadIdx.y;  // 32 x 8
    #pragma unroll
    for (int j = 0; j < 4; j++) {
        int s = s0 + ty + j * 8;
        t[ty + j * 8][tx] = g_v[((size_t)b * NS + s) * NC + c0 + tx];
    }
    __syncthreads();
    #pragma unroll
    for (int j = 0; j < 4; j++) {
        int c = c0 + ty + j * 8;
        g_vtf[((size_t)b * NC + c) * NS + s0 + tx] = __float2half_rn(t[tx][ty + j * 8]);
    }
}

// ---------------- launch ----------------
extern "C" void kernel_launch(void* const* d_in, const int* in_sizes, int n_in,
                              void* d_out, int out_size)
{
    const float* x    = (const float*)d_in[0];
    const float* rope = (const float*)d_in[1];
    const float* Wq   = (const float*)d_in[2];
    const float* bq   = (const float*)d_in[3];
    const float* Wk   = (const float*)d_in[4];
    const float* bk   = (const float*)d_in[5];
    const float* Wv   = (const float*)d_in[6];
    const float* bv   = (const float*)d_in[7];
    const float* gq   = (const float*)d_in[8];
    const float* gk   = (const float*)d_in[9];
    const float* Wo   = (const float*)d_in[10];
    const float* bo   = (const float*)d_in[11];
    float* out = (float*)d_out;

    cudaFuncSetAttribute(k_gemm_f16<0>, cudaFuncAttributeMaxDynamicSharedMemorySize, F16_SMEM);
    cudaFuncSetAttribute(k_gemm_f16<1>, cudaFuncAttributeMaxDynamicSharedMemorySize, F16_SMEM);
    cudaFuncSetAttribute(k_gemm_f16<2>, cudaFuncAttributeMaxDynamicSharedMemorySize, F16_SMEM);
    cudaFuncSetAttribute(k_flash, cudaFuncAttributeMaxDynamicSharedMemorySize, FLASH_SMEM);

    float *vp;
    f16 *xhf, *xlf, *wqf, *wkf, *wvf, *wof, *chf, *clf, *qhf, *qlf, *kf;
    cudaGetSymbolAddress((void**)&vp, g_v);
    cudaGetSymbolAddress((void**)&xhf, g_xhf); cudaGetSymbolAddress((void**)&xlf, g_xlf);
    cudaGetSymbolAddress((void**)&wqf, g_wqf); cudaGetSymbolAddress((void**)&wkf, g_wkf);
    cudaGetSymbolAddress((void**)&wvf, g_wvf); cudaGetSymbolAddress((void**)&wof, g_wof);
    cudaGetSymbolAddress((void**)&chf, g_chf); cudaGetSymbolAddress((void**)&clf, g_clf);
    cudaGetSymbolAddress((void**)&qhf, g_qhf); cudaGetSymbolAddress((void**)&qlf, g_qlf);
    cudaGetSymbolAddress((void**)&kf, g_kf);

    const size_t nX = (size_t)NM * NC;       // 8M elems
    const size_t nW = (size_t)NC * NC;       // 4M elems

    cvt_split_f16<<<(unsigned)(nX / 1024), 256>>>(x, xhf, xlf);
    cvt_f16_w<<<dim3((unsigned)(nW / 1024), 4), 256>>>(Wq, Wk, Wv, Wo,
                                                       wqf, wkf, wvf, wof);

    dim3 gProj(NC / 128, NM / 128);          // (16, 32)
    // Q: fused RMSNorm+RoPE -> split f16
    k_gemm_f16<1><<<gProj, 256, F16_SMEM>>>(xhf, xlf, wqf, bq,
                                            nullptr, qhf, qlf, rope, gq);
    // K: fused RMSNorm+RoPE -> single f16
    k_gemm_f16<2><<<gProj, 256, F16_SMEM>>>(xhf, xlf, wkf, bk,
                                            nullptr, kf, nullptr, rope, gk);
    // V: plain fp32
    k_gemm_f16<0><<<gProj, 256, F16_SMEM>>>(xhf, xlf, wvf, bv,
                                            vp, nullptr, nullptr, nullptr, nullptr);

    transpose_v_f16<<<dim3(NS / 32, NC / 32, NB), dim3(32, 8)>>>();

    k_flash<<<dim3(NS / 128, NBH), 256, FLASH_SMEM>>>();

    // out-proj: plain fp32 to harness output
    k_gemm_f16<0><<<gProj, 256, F16_SMEM>>>(chf, clf, wof, bo,
                                            out, nullptr, nullptr, nullptr, nullptr);
}

// round 15
// speedup vs baseline: 1.1263x; 1.0327x over previous
#include <cuda_runtime.h>
#include <cuda_bf16.h>
#include <cuda_fp16.h>
#include <math.h>
#include <stdint.h>
#include <stddef.h>

#define NB 2
#define NS 2048
#define NC 2048
#define ND 128
#define NH 16
#define NM (NB * NS)       // 4096
#define NBH (NB * NH)      // 32
#define RMS_EPS 1.1920928955078125e-07f
#define SM_SCALE 0.08838834764831844f

typedef __half f16;

// ---------------- scratch (device globals; no allocation) ----------------
__device__ float g_v[(size_t)NM * NC];

// f16 operands
__device__ f16 g_xhf[(size_t)NM * NC], g_xlf[(size_t)NM * NC];
__device__ f16 g_wqf[(size_t)NC * NC], g_wkf[(size_t)NC * NC];
__device__ f16 g_wvf[(size_t)NC * NC], g_wof[(size_t)NC * NC];
__device__ f16 g_vtf[(size_t)NB * NC * NS];
__device__ f16 g_chf[(size_t)NM * NC], g_clf[(size_t)NM * NC];
__device__ f16 g_qhf[(size_t)NM * NC], g_qlf[(size_t)NM * NC];   // Q split 2xf16
__device__ f16 g_kf[(size_t)NM * NC];                            // K single f16

// ---------------- PTX helpers (sm_80-era, family-target safe) -------------
__device__ __forceinline__ uint32_t smem_to_u32(const void* p) {
    uint32_t a;
    asm("{ .reg .u64 t; cvta.to.shared.u64 t, %1; cvt.u32.u64 %0, t; }"
        : "=r"(a) : "l"(p));
    return a;
}
__device__ __forceinline__ void cp_async16(uint32_t dst, const void* src) {
    asm volatile("cp.async.cg.shared.global [%0], [%1], 16;"
                 :: "r"(dst), "l"(src) : "memory");
}
__device__ __forceinline__ void cp_commit() {
    asm volatile("cp.async.commit_group;" ::: "memory");
}
template <int N>
__device__ __forceinline__ void cp_wait() {
    asm volatile("cp.async.wait_group %0;" :: "n"(N) : "memory");
}
__device__ __forceinline__ void ldm_x4(uint32_t (&r)[4], uint32_t addr) {
    asm volatile("ldmatrix.sync.aligned.m8n8.x4.shared.b16 {%0,%1,%2,%3}, [%4];"
                 : "=r"(r[0]), "=r"(r[1]), "=r"(r[2]), "=r"(r[3]) : "r"(addr));
}
__device__ __forceinline__ void mma_f16(float (&d)[4], const uint32_t (&a)[4],
                                        uint32_t b0, uint32_t b1) {
    asm volatile("mma.sync.aligned.m16n8k16.row.col.f32.f16.f16.f32 "
                 "{%0,%1,%2,%3}, {%4,%5,%6,%7}, {%8,%9}, {%0,%1,%2,%3};"
                 : "+f"(d[0]), "+f"(d[1]), "+f"(d[2]), "+f"(d[3])
                 : "r"(a[0]), "r"(a[1]), "r"(a[2]), "r"(a[3]), "r"(b0), "r"(b1));
}

__device__ __forceinline__ void split2f(float x, f16& h, f16& l) {
    h = __float2half_rn(x);
    l = __float2half_rn(x - __half2float(h));
}
__device__ __forceinline__ uint32_t pack_f16x2(float x, float y) {
    __half2 H = __floats2half2_rn(x, y);
    return *reinterpret_cast<uint32_t*>(&H);
}

// ---------------- common tiling constants ----------------
#define KCH 32
#define ROW_BYTES 80
#define TILE_BYTES (128 * ROW_BYTES)        // 10240

__device__ __forceinline__ void load_tile_async(uint32_t smbase, const void* g,
                                                int ld, int k0, int tid) {
    const char* gp = (const char*)g + (size_t)k0 * 2;
    #pragma unroll
    for (int j = 0; j < 2; j++) {
        int i = tid + j * 256;
        int row = i >> 2;
        int c = i & 3;
        cp_async16(smbase + row * ROW_BYTES + c * 16,
                   gp + (size_t)row * ld * 2 + c * 16);
    }
}

// =========================================================================
// f16 2-term GEMM: A split 2xf16, B single f16. R11 tiling (32x64 warp
// tile, 8 warps, 3-stage pipeline). __launch_bounds__(256,2) caps regs at
// 128 so 2 CTAs/SM always fit (R14's fused epilogue hit 136 regs -> 1 CTA).
// MODE 0: fp32 out + bias (V proj, out-proj)
// MODE 1: fused bias + per-head RMSNorm + RoPE -> split f16 (Q)
// MODE 2: fused bias + per-head RMSNorm + RoPE -> single f16 (K)
// =========================================================================
#define F16_STAGE (3 * TILE_BYTES)          // 30720
#define F16_SMEM (3 * F16_STAGE)            // 92160

template <int MODE>
__global__ __launch_bounds__(256, 2)
void k_gemm_f16(const f16* __restrict__ AhG, const f16* __restrict__ AlG,
                const f16* __restrict__ BfG, const float* __restrict__ biasG,
                float* __restrict__ OutFG,
                f16* __restrict__ OutHG, f16* __restrict__ OutLG,
                const float* __restrict__ rope, const float* __restrict__ gamma)
{
    size_t bm = (size_t)blockIdx.y * 128;
    size_t bn = (size_t)blockIdx.x * 128;
    const f16* Ah = AhG + bm * NC;
    const f16* Al = AlG + bm * NC;
    const f16* Bf = BfG + bn * NC;
    const float* bias = biasG + bn;

    extern __shared__ char sm[];
    uint32_t sb = smem_to_u32(sm);
    const int tid = threadIdx.x;             // 256 threads = 8 warps
    const int lane = tid & 31;
    const int warp = tid >> 5;
    const int wm = warp >> 1;                // 0..3  rows: wm*32
    const int wn = warp & 1;                 // 0..1  cols: wn*64

    float acc[2][8][4];
    #pragma unroll
    for (int mt = 0; mt < 2; mt++)
        #pragma unroll
        for (int nt = 0; nt < 8; nt++)
            #pragma unroll
            for (int j = 0; j < 4; j++) acc[mt][nt][j] = 0.0f;

    const int nch = NC / KCH;

    auto load_chunk = [&](int ch, int s) {
        uint32_t base = sb + s * F16_STAGE;
        int k0 = ch * KCH;
        load_tile_async(base,                  Ah, NC, k0, tid);
        load_tile_async(base + TILE_BYTES,     Al, NC, k0, tid);
        load_tile_async(base + 2 * TILE_BYTES, Bf, NC, k0, tid);
    };

    load_chunk(0, 0);
    cp_commit();
    load_chunk(1, 1);
    cp_commit();

    int stage = 0;
    for (int ch = 0; ch < nch; ch++) {
        if (ch + 1 < nch) cp_wait<1>(); else cp_wait<0>();
        __syncthreads();
        if (ch + 2 < nch) {
            int ns = stage + 2;
            if (ns >= 3) ns -= 3;
            load_chunk(ch + 2, ns);
            cp_commit();
        }

        uint32_t base = sb + stage * F16_STAGE;
        if (++stage == 3) stage = 0;

        #pragma unroll
        for (int ks = 0; ks < 2; ks++) {
            uint32_t koff = (uint32_t)(ks * 32 + (lane >> 4) * 16);
            uint32_t ah[2][4], al[2][4];
            #pragma unroll
            for (int mt = 0; mt < 2; mt++) {
                uint32_t r = wm * 32 + mt * 16 + (lane & 15);
                uint32_t addr = base + r * ROW_BYTES + koff;
                ldm_x4(ah[mt], addr);
                ldm_x4(al[mt], addr + TILE_BYTES);
            }
            uint32_t bfr[4][4];
            #pragma unroll
            for (int ng = 0; ng < 4; ng++) {
                uint32_t r = wn * 64 + ng * 16 + (lane & 15);
                ldm_x4(bfr[ng], base + 2 * TILE_BYTES + r * ROW_BYTES + koff);
            }
            #pragma unroll
            for (int mt = 0; mt < 2; mt++)
                #pragma unroll
                for (int ng = 0; ng < 4; ng++) {
                    mma_f16(acc[mt][2 * ng],     ah[mt], bfr[ng][0], bfr[ng][2]);
                    mma_f16(acc[mt][2 * ng],     al[mt], bfr[ng][0], bfr[ng][2]);
                    mma_f16(acc[mt][2 * ng + 1], ah[mt], bfr[ng][1], bfr[ng][3]);
                    mma_f16(acc[mt][2 * ng + 1], al[mt], bfr[ng][1], bfr[ng][3]);
                }
        }
    }

    // fold bias into acc
    #pragma unroll
    for (int mt = 0; mt < 2; mt++)
        #pragma unroll
        for (int nt = 0; nt < 8; nt++) {
            int c = wn * 64 + nt * 8 + (lane & 3) * 2;
            float bx = bias[c], by = bias[c + 1];
            acc[mt][nt][0] += bx; acc[mt][nt][1] += by;
            acc[mt][nt][2] += bx; acc[mt][nt][3] += by;
        }

    if (MODE == 0) {
        float* Out = OutFG + bm * NC + bn;
        #pragma unroll
        for (int mt = 0; mt < 2; mt++) {
            int r0 = wm * 32 + mt * 16 + (lane >> 2);
            #pragma unroll
            for (int nt = 0; nt < 8; nt++) {
                int c = wn * 64 + nt * 8 + (lane & 3) * 2;
                float2 v0 = { acc[mt][nt][0], acc[mt][nt][1] };
                float2 v1 = { acc[mt][nt][2], acc[mt][nt][3] };
                *(float2*)(Out + (size_t)r0 * NC + c) = v0;
                *(float2*)(Out + (size_t)(r0 + 8) * NC + c) = v1;
            }
        }
    } else {
        // fused per-head RMSNorm + RoPE (tile == one head)
        __syncthreads();                     // pipeline smem reads done
        float* sums = (float*)sm;            // [2][128]
        #pragma unroll
        for (int mt = 0; mt < 2; mt++) {
            float ss0 = 0.f, ss1 = 0.f;
            #pragma unroll
            for (int nt = 0; nt < 8; nt++) {
                ss0 += acc[mt][nt][0] * acc[mt][nt][0]
                     + acc[mt][nt][1] * acc[mt][nt][1];
                ss1 += acc[mt][nt][2] * acc[mt][nt][2]
                     + acc[mt][nt][3] * acc[mt][nt][3];
            }
            ss0 += __shfl_xor_sync(0xffffffffu, ss0, 1);
            ss0 += __shfl_xor_sync(0xffffffffu, ss0, 2);
            ss1 += __shfl_xor_sync(0xffffffffu, ss1, 1);
            ss1 += __shfl_xor_sync(0xffffffffu, ss1, 2);
            int r0 = wm * 32 + mt * 16 + (lane >> 2);
            if ((lane & 3) == 0) {
                sums[wn * 128 + r0] = ss0;
                sums[wn * 128 + r0 + 8] = ss1;
            }
        }
        __syncthreads();
        #pragma unroll
        for (int mt = 0; mt < 2; mt++) {
            int r0 = wm * 32 + mt * 16 + (lane >> 2);
            int m0 = (int)bm + r0, m1 = m0 + 8;
            int s0 = m0 & (NS - 1), s1 = m1 & (NS - 1);
            float rq0 = rsqrtf((sums[r0] + sums[128 + r0]) * (1.0f / ND) + RMS_EPS);
            float rq1 = rsqrtf((sums[r0 + 8] + sums[128 + r0 + 8]) * (1.0f / ND) + RMS_EPS);
            #pragma unroll
            for (int nt = 0; nt < 8; nt++) {
                int c = wn * 64 + nt * 8 + (lane & 3) * 2;
                float g0 = gamma[c], g1 = gamma[c + 1];
                float4 rp0 = *(const float4*)(rope + (size_t)s0 * 256 + c * 2);
                float4 rp1 = *(const float4*)(rope + (size_t)s1 * 256 + c * 2);
                float x0 = acc[mt][nt][0] * rq0 * g0;
                float x1 = acc[mt][nt][1] * rq0 * g1;
                float y0 = rp0.x * x0 + rp0.y * x1;
                float y1 = rp0.z * x0 + rp0.w * x1;
                float x2 = acc[mt][nt][2] * rq1 * g0;
                float x3 = acc[mt][nt][3] * rq1 * g1;
                float y2 = rp1.x * x2 + rp1.y * x3;
                float y3 = rp1.z * x2 + rp1.w * x3;
                size_t o0 = (size_t)m0 * NC + bn + c;
                size_t o1 = (size_t)m1 * NC + bn + c;
                if (MODE == 1) {
                    f16 h0, l0, h1, l1;
                    split2f(y0, h0, l0); split2f(y1, h1, l1);
                    *(__half2*)(OutHG + o0) = __half2{h0, h1};
                    *(__half2*)(OutLG + o0) = __half2{l0, l1};
                    split2f(y2, h0, l0); split2f(y3, h1, l1);
                    *(__half2*)(OutHG + o1) = __half2{h0, h1};
                    *(__half2*)(OutLG + o1) = __half2{l0, l1};
                } else {
                    *(__half2*)(OutHG + o0) = __floats2half2_rn(y0, y1);
                    *(__half2*)(OutHG + o1) = __floats2half2_rn(y2, y3);
                }
            }
        }
    }
}

// =========================================================================
// Flash attention: scores (f16 2-term) + online softmax + PV (f16 1-term)
// Double-buffered K AND V (unchanged from R11).
// =========================================================================
#define FT_ROWB 272                          // 256B row + 16B pad
#define FT_TILE (128 * FT_ROWB)              // 34816
#define OFF_K 0
#define OFF_V (2 * FT_TILE)
#define FLASH_SMEM (4 * FT_TILE)             // 139264

__device__ __forceinline__ void fa_load_one(uint32_t dst, const f16* g,
                                            size_t rowbase, size_t ldrow, int tid)
{
    #pragma unroll
    for (int i = 0; i < 8; i++) {
        int idx = tid + i * 256;
        int row = idx >> 4;
        int ch = idx & 15;
        cp_async16(dst + row * FT_ROWB + ch * 16,
                   (const char*)(g + rowbase + (size_t)row * ldrow) + ch * 16);
    }
}

__global__ void __launch_bounds__(256, 1) k_flash()
{
    extern __shared__ char sm[];
    uint32_t sb = smem_to_u32(sm);
    const int tid = threadIdx.x;
    const int lane = tid & 31;
    const int warp = tid >> 5;
    const int q0 = blockIdx.x * 128;
    const int bh = blockIdx.y, b = bh >> 4, h = bh & 15;

    const size_t kbase = (size_t)(b * NS) * NC + (size_t)h * ND;
    const size_t vbase = ((size_t)b * NC + (size_t)h * ND) * NS;

    size_t qbase = (size_t)(b * NS + q0) * NC + (size_t)h * ND;
    fa_load_one(sb + OFF_K, g_qhf, qbase, NC, tid);
    fa_load_one(sb + OFF_V, g_qlf, qbase, NC, tid);
    cp_commit();                                        // group: Q
    fa_load_one(sb + OFF_K + FT_TILE, g_kf, kbase, NC, tid);
    fa_load_one(sb + OFF_V + FT_TILE, g_vtf, vbase, NS, tid);
    cp_commit();                                        // group: K0,V0
    cp_wait<1>();                                       // Q ready
    __syncthreads();

    uint32_t qhf[8][4], qlf[8][4];
    {
        uint32_t rbase = sb + (warp * 16 + (lane & 15)) * FT_ROWB + ((lane >> 4) << 4);
        #pragma unroll
        for (int ks = 0; ks < 8; ks++) {
            ldm_x4(qhf[ks], rbase + OFF_K + ks * 32);
            ldm_x4(qlf[ks], rbase + OFF_V + ks * 32);
        }
    }
    __syncthreads();                                    // Q buffers free

    fa_load_one(sb + OFF_K, g_kf, kbase + (size_t)128 * NC, NC, tid);
    fa_load_one(sb + OFF_V, g_vtf, vbase + 128, NS, tid);
    cp_commit();                                        // group: K1,V1

    float o[16][4];
    #pragma unroll
    for (int i = 0; i < 16; i++) { o[i][0] = 0.f; o[i][1] = 0.f; o[i][2] = 0.f; o[i][3] = 0.f; }
    float m0 = -1e30f, m1 = -1e30f, l0 = 0.f, l1 = 0.f;

    for (int j = 0; j < 16; j++) {
        if (j + 1 < 16) cp_wait<1>(); else cp_wait<0>();
        __syncthreads();

        uint32_t bufo = (uint32_t)((j + 1) & 1) * FT_TILE;

        float s[16][4];
        #pragma unroll
        for (int i = 0; i < 16; i++) { s[i][0] = 0.f; s[i][1] = 0.f; s[i][2] = 0.f; s[i][3] = 0.f; }
        #pragma unroll
        for (int ng = 0; ng < 8; ng++) {
            #pragma unroll
            for (int ks = 0; ks < 8; ks++) {
                uint32_t addr = sb + OFF_K + bufo + (ng * 16 + (lane & 15)) * FT_ROWB
                              + ((lane >> 4) << 4) + ks * 32;
                uint32_t kf4[4];
                ldm_x4(kf4, addr);
                mma_f16(s[2 * ng],     qhf[ks], kf4[0], kf4[2]);
                mma_f16(s[2 * ng],     qlf[ks], kf4[0], kf4[2]);
                mma_f16(s[2 * ng + 1], qhf[ks], kf4[1], kf4[3]);
                mma_f16(s[2 * ng + 1], qlf[ks], kf4[1], kf4[3]);
            }
        }

        float mx0 = -1e30f, mx1 = -1e30f;
        #pragma unroll
        for (int i = 0; i < 16; i++) {
            mx0 = fmaxf(mx0, fmaxf(s[i][0], s[i][1]));
            mx1 = fmaxf(mx1, fmaxf(s[i][2], s[i][3]));
        }
        mx0 = fmaxf(mx0, __shfl_xor_sync(0xffffffffu, mx0, 1));
        mx0 = fmaxf(mx0, __shfl_xor_sync(0xffffffffu, mx0, 2));
        mx1 = fmaxf(mx1, __shfl_xor_sync(0xffffffffu, mx1, 1));
        mx1 = fmaxf(mx1, __shfl_xor_sync(0xffffffffu, mx1, 2));
        float nm0 = fmaxf(m0, mx0), nm1 = fmaxf(m1, mx1);
        float a0 = __expf((m0 - nm0) * SM_SCALE);
        float a1 = __expf((m1 - nm1) * SM_SCALE);
        m0 = nm0; m1 = nm1;
        float ps0 = 0.f, ps1 = 0.f;
        #pragma unroll
        for (int i = 0; i < 16; i++) {
            s[i][0] = __expf((s[i][0] - m0) * SM_SCALE);
            s[i][1] = __expf((s[i][1] - m0) * SM_SCALE);
            s[i][2] = __expf((s[i][2] - m1) * SM_SCALE);
            s[i][3] = __expf((s[i][3] - m1) * SM_SCALE);
            ps0 += s[i][0] + s[i][1];
            ps1 += s[i][2] + s[i][3];
        }
        l0 = l0 * a0 + ps0;
        l1 = l1 * a1 + ps1;
        #pragma unroll
        for (int i = 0; i < 16; i++) {
            o[i][0] *= a0; o[i][1] *= a0; o[i][2] *= a1; o[i][3] *= a1;
        }

        #pragma unroll
        for (int ks = 0; ks < 8; ks++) {
            uint32_t pa[4];
            pa[0] = pack_f16x2(s[2 * ks][0],     s[2 * ks][1]);
            pa[1] = pack_f16x2(s[2 * ks][2],     s[2 * ks][3]);
            pa[2] = pack_f16x2(s[2 * ks + 1][0], s[2 * ks + 1][1]);
            pa[3] = pack_f16x2(s[2 * ks + 1][2], s[2 * ks + 1][3]);
            #pragma unroll
            for (int ng = 0; ng < 8; ng++) {
                uint32_t addr = sb + OFF_V + bufo + (ng * 16 + (lane & 15)) * FT_ROWB
                              + ((lane >> 4) << 4) + ks * 32;
                uint32_t vf4[4];
                ldm_x4(vf4, addr);
                mma_f16(o[2 * ng],     pa, vf4[0], vf4[2]);
                mma_f16(o[2 * ng + 1], pa, vf4[1], vf4[3]);
            }
        }

        __syncthreads();
        if (j + 2 < 16) {
            fa_load_one(sb + OFF_K + bufo, g_kf,
                        kbase + (size_t)(j + 2) * 128 * NC, NC, tid);
            fa_load_one(sb + OFF_V + bufo, g_vtf,
                        vbase + (size_t)(j + 2) * 128, NS, tid);
            cp_commit();
        }
    }

    l0 += __shfl_xor_sync(0xffffffffu, l0, 1);
    l0 += __shfl_xor_sync(0xffffffffu, l0, 2);
    l1 += __shfl_xor_sync(0xffffffffu, l1, 1);
    l1 += __shfl_xor_sync(0xffffffffu, l1, 2);
    float i0 = 1.0f / l0, i1 = 1.0f / l1;

    size_t gr0 = (size_t)(b * NS + q0 + warp * 16 + (lane >> 2));
    #pragma unroll
    for (int nt = 0; nt < 16; nt++) {
        int c = h * ND + nt * 8 + (lane & 3) * 2;
        f16 h0, h1, lo0, lo1;
        split2f(o[nt][0] * i0, h0, lo0);
        split2f(o[nt][1] * i0, h1, lo1);
        *(__half2*)(g_chf + gr0 * NC + c) = __half2{h0, h1};
        *(__half2*)(g_clf + gr0 * NC + c) = __half2{lo0, lo1};
        split2f(o[nt][2] * i1, h0, lo0);
        split2f(o[nt][3] * i1, h1, lo1);
        *(__half2*)(g_chf + (gr0 + 8) * NC + c) = __half2{h0, h1};
        *(__half2*)(g_clf + (gr0 + 8) * NC + c) = __half2{lo0, lo1};
    }
}

// ---------------- elementwise kernels ----------------
__global__ __launch_bounds__(256) void cvt_split_f16(const float* __restrict__ src,
                                                     f16* __restrict__ hi,
                                                     f16* __restrict__ lo)
{
    size_t i = (size_t)blockIdx.x * 256 + threadIdx.x;
    float4 v = ((const float4*)src)[i];
    f16 h0, h1, h2, h3, l0, l1, l2, l3;
    split2f(v.x, h0, l0); split2f(v.y, h1, l1);
    split2f(v.z, h2, l2); split2f(v.w, h3, l3);
    __half2* hp = (__half2*)hi;
    __half2* lp = (__half2*)lo;
    hp[2 * i]     = __half2{h0, h1};
    hp[2 * i + 1] = __half2{h2, h3};
    lp[2 * i]     = __half2{l0, l1};
    lp[2 * i + 1] = __half2{l2, l3};
}

// Convert the 4 weight matrices in one launch: blockIdx.y selects tensor.
__global__ __launch_bounds__(256) void cvt_f16_w(
    const float* __restrict__ s0, const float* __restrict__ s1,
    const float* __restrict__ s2, const float* __restrict__ s3,
    f16* __restrict__ d0, f16* __restrict__ d1,
    f16* __restrict__ d2, f16* __restrict__ d3)
{
    const float* src = (blockIdx.y == 0) ? s0 : (blockIdx.y == 1) ? s1
                     : (blockIdx.y == 2) ? s2 : s3;
    f16* dst = (blockIdx.y == 0) ? d0 : (blockIdx.y == 1) ? d1
             : (blockIdx.y == 2) ? d2 : d3;
    size_t i = (size_t)blockIdx.x * 256 + threadIdx.x;
    float4 v = ((const float4*)src)[i];
    __half2* dp = (__half2*)dst;
    dp[2 * i]     = __floats2half2_rn(v.x, v.y);
    dp[2 * i + 1] = __floats2half2_rn(v.z, v.w);
}

// V transpose to single f16: g_v[(b*S+s), c] -> vT[(b*C+c), s]
__global__ __launch_bounds__(256) void transpose_v_f16()
{
    __shared__ float t[32][33];
    int b = blockIdx.z;
    int s0 = blockIdx.x * 32, c0 = blockIdx.y * 32;
    int tx = threadIdx.x, ty = threadIdx.y;  // 32 x 8
    #pragma unroll
    for (int j = 0; j < 4; j++) {
        int s = s0 + ty + j * 8;
        t[ty + j * 8][tx] = g_v[((size_t)b * NS + s) * NC + c0 + tx];
    }
    __syncthreads();
    #pragma unroll
    for (int j = 0; j < 4; j++) {
        int c = c0 + ty + j * 8;
        g_vtf[((size_t)b * NC + c) * NS + s0 + tx] = __float2half_rn(t[tx][ty + j * 8]);
    }
}

// ---------------- launch ----------------
extern "C" void kernel_launch(void* const* d_in, const int* in_sizes, int n_in,
                              void* d_out, int out_size)
{
    const float* x    = (const float*)d_in[0];
    const float* rope = (const float*)d_in[1];
    const float* Wq   = (const float*)d_in[2];
    const float* bq   = (const float*)d_in[3];
    const float* Wk   = (const float*)d_in[4];
    const float* bk   = (const float*)d_in[5];
    const float* Wv   = (const float*)d_in[6];
    const float* bv   = (const float*)d_in[7];
    const float* gq   = (const float*)d_in[8];
    const float* gk   = (const float*)d_in[9];
    const float* Wo   = (const float*)d_in[10];
    const float* bo   = (const float*)d_in[11];
    float* out = (float*)d_out;

    cudaFuncSetAttribute(k_gemm_f16<0>, cudaFuncAttributeMaxDynamicSharedMemorySize, F16_SMEM);
    cudaFuncSetAttribute(k_gemm_f16<1>, cudaFuncAttributeMaxDynamicSharedMemorySize, F16_SMEM);
    cudaFuncSetAttribute(k_gemm_f16<2>, cudaFuncAttributeMaxDynamicSharedMemorySize, F16_SMEM);
    cudaFuncSetAttribute(k_flash, cudaFuncAttributeMaxDynamicSharedMemorySize, FLASH_SMEM);

    float *vp;
    f16 *xhf, *xlf, *wqf, *wkf, *wvf, *wof, *chf, *clf, *qhf, *qlf, *kf;
    cudaGetSymbolAddress((void**)&vp, g_v);
    cudaGetSymbolAddress((void**)&xhf, g_xhf); cudaGetSymbolAddress((void**)&xlf, g_xlf);
    cudaGetSymbolAddress((void**)&wqf, g_wqf); cudaGetSymbolAddress((void**)&wkf, g_wkf);
    cudaGetSymbolAddress((void**)&wvf, g_wvf); cudaGetSymbolAddress((void**)&wof, g_wof);
    cudaGetSymbolAddress((void**)&chf, g_chf); cudaGetSymbolAddress((void**)&clf, g_clf);
    cudaGetSymbolAddress((void**)&qhf, g_qhf); cudaGetSymbolAddress((void**)&qlf, g_qlf);
    cudaGetSymbolAddress((void**)&kf, g_kf);

    const size_t nX = (size_t)NM * NC;       // 8M elems
    const size_t nW = (size_t)NC * NC;       // 4M elems

    cvt_split_f16<<<(unsigned)(nX / 1024), 256>>>(x, xhf, xlf);
    cvt_f16_w<<<dim3((unsigned)(nW / 1024), 4), 256>>>(Wq, Wk, Wv, Wo,
                                                       wqf, wkf, wvf, wof);

    dim3 gProj(NC / 128, NM / 128);          // (16, 32)
    // Q: fused RMSNorm+RoPE -> split f16
    k_gemm_f16<1><<<gProj, 256, F16_SMEM>>>(xhf, xlf, wqf, bq,
                                            nullptr, qhf, qlf, rope, gq);
    // K: fused RMSNorm+RoPE -> single f16
    k_gemm_f16<2><<<gProj, 256, F16_SMEM>>>(xhf, xlf, wkf, bk,
                                            nullptr, kf, nullptr, rope, gk);
    // V: plain fp32
    k_gemm_f16<0><<<gProj, 256, F16_SMEM>>>(xhf, xlf, wvf, bv,
                                            vp, nullptr, nullptr, nullptr, nullptr);

    transpose_v_f16<<<dim3(NS / 32, NC / 32, NB), dim3(32, 8)>>>();

    k_flash<<<dim3(NS / 128, NBH), 256, FLASH_SMEM>>>();

    // out-proj: plain fp32 to harness output
    k_gemm_f16<0><<<gProj, 256, F16_SMEM>>>(chf, clf, wof, bo,
                                            out, nullptr, nullptr, nullptr, nullptr);
}

// round 16
// speedup vs baseline: 1.1331x; 1.0060x over previous
#include <cuda_runtime.h>
#include <cuda_bf16.h>
#include <cuda_fp16.h>
#include <math.h>
#include <stdint.h>
#include <stddef.h>

#define NB 2
#define NS 2048
#define NC 2048
#define ND 128
#define NH 16
#define NM (NB * NS)       // 4096
#define NBH (NB * NH)      // 32
#define RMS_EPS 1.1920928955078125e-07f
#define SM_SCALE 0.08838834764831844f

typedef __half f16;

// ---------------- scratch (device globals; no allocation) ----------------
// f16 operands
__device__ f16 g_xhf[(size_t)NM * NC], g_xlf[(size_t)NM * NC];
__device__ f16 g_wqf[(size_t)NC * NC], g_wkf[(size_t)NC * NC];
__device__ f16 g_wvf[(size_t)NC * NC], g_wof[(size_t)NC * NC];
__device__ f16 g_vtf[(size_t)NB * NC * NS];
__device__ f16 g_chf[(size_t)NM * NC], g_clf[(size_t)NM * NC];
__device__ f16 g_qhf[(size_t)NM * NC], g_qlf[(size_t)NM * NC];   // Q split 2xf16
__device__ f16 g_kf[(size_t)NM * NC];                            // K single f16

// ---------------- PTX helpers (sm_80-era, family-target safe) -------------
__device__ __forceinline__ uint32_t smem_to_u32(const void* p) {
    uint32_t a;
    asm("{ .reg .u64 t; cvta.to.shared.u64 t, %1; cvt.u32.u64 %0, t; }"
        : "=r"(a) : "l"(p));
    return a;
}
__device__ __forceinline__ void cp_async16(uint32_t dst, const void* src) {
    asm volatile("cp.async.cg.shared.global [%0], [%1], 16;"
                 :: "r"(dst), "l"(src) : "memory");
}
__device__ __forceinline__ void cp_commit() {
    asm volatile("cp.async.commit_group;" ::: "memory");
}
template <int N>
__device__ __forceinline__ void cp_wait() {
    asm volatile("cp.async.wait_group %0;" :: "n"(N) : "memory");
}
__device__ __forceinline__ void ldm_x4(uint32_t (&r)[4], uint32_t addr) {
    asm volatile("ldmatrix.sync.aligned.m8n8.x4.shared.b16 {%0,%1,%2,%3}, [%4];"
                 : "=r"(r[0]), "=r"(r[1]), "=r"(r[2]), "=r"(r[3]) : "r"(addr));
}
__device__ __forceinline__ void mma_f16(float (&d)[4], const uint32_t (&a)[4],
                                        uint32_t b0, uint32_t b1) {
    asm volatile("mma.sync.aligned.m16n8k16.row.col.f32.f16.f16.f32 "
                 "{%0,%1,%2,%3}, {%4,%5,%6,%7}, {%8,%9}, {%0,%1,%2,%3};"
                 : "+f"(d[0]), "+f"(d[1]), "+f"(d[2]), "+f"(d[3])
                 : "r"(a[0]), "r"(a[1]), "r"(a[2]), "r"(a[3]), "r"(b0), "r"(b1));
}

__device__ __forceinline__ void split2f(float x, f16& h, f16& l) {
    h = __float2half_rn(x);
    l = __float2half_rn(x - __half2float(h));
}
__device__ __forceinline__ uint32_t pack_f16x2(float x, float y) {
    __half2 H = __floats2half2_rn(x, y);
    return *reinterpret_cast<uint32_t*>(&H);
}

// ---------------- common tiling constants ----------------
#define KCH 32
#define ROW_BYTES 80
#define TILE_BYTES (128 * ROW_BYTES)        // 10240

__device__ __forceinline__ void load_tile_async(uint32_t smbase, const void* g,
                                                int ld, int k0, int tid) {
    const char* gp = (const char*)g + (size_t)k0 * 2;
    #pragma unroll
    for (int j = 0; j < 2; j++) {
        int i = tid + j * 256;
        int row = i >> 2;
        int c = i & 3;
        cp_async16(smbase + row * ROW_BYTES + c * 16,
                   gp + (size_t)row * ld * 2 + c * 16);
    }
}

// =========================================================================
// f16 2-term GEMM: A split 2xf16, B single f16. R11 tiling (32x64 warp
// tile, 8 warps, 3-stage pipeline). __launch_bounds__(256,2) caps regs at
// 128 so 2 CTAs/SM always fit.
// MODE 0: fp32 out + bias (out-proj)
// MODE 1: fused bias + per-head RMSNorm + RoPE -> split f16 (Q)
// MODE 2: fused bias + per-head RMSNorm + RoPE -> single f16 (K)
// MODE 3: fused bias + transpose -> f16 V^T tile (V), via smem staging
// =========================================================================
#define F16_STAGE (3 * TILE_BYTES)          // 30720
#define F16_SMEM (3 * F16_STAGE)            // 92160
#define TV_STRIDE 130                        // f16 units; conflict-light

template <int MODE>
__global__ __launch_bounds__(256, 2)
void k_gemm_f16(const f16* __restrict__ AhG, const f16* __restrict__ AlG,
                const f16* __restrict__ BfG, const float* __restrict__ biasG,
                float* __restrict__ OutFG,
                f16* __restrict__ OutHG, f16* __restrict__ OutLG,
                const float* __restrict__ rope, const float* __restrict__ gamma)
{
    size_t bm = (size_t)blockIdx.y * 128;
    size_t bn = (size_t)blockIdx.x * 128;
    const f16* Ah = AhG + bm * NC;
    const f16* Al = AlG + bm * NC;
    const f16* Bf = BfG + bn * NC;
    const float* bias = biasG + bn;

    extern __shared__ char sm[];
    uint32_t sb = smem_to_u32(sm);
    const int tid = threadIdx.x;             // 256 threads = 8 warps
    const int lane = tid & 31;
    const int warp = tid >> 5;
    const int wm = warp >> 1;                // 0..3  rows: wm*32
    const int wn = warp & 1;                 // 0..1  cols: wn*64

    float acc[2][8][4];
    #pragma unroll
    for (int mt = 0; mt < 2; mt++)
        #pragma unroll
        for (int nt = 0; nt < 8; nt++)
            #pragma unroll
            for (int j = 0; j < 4; j++) acc[mt][nt][j] = 0.0f;

    const int nch = NC / KCH;

    auto load_chunk = [&](int ch, int s) {
        uint32_t base = sb + s * F16_STAGE;
        int k0 = ch * KCH;
        load_tile_async(base,                  Ah, NC, k0, tid);
        load_tile_async(base + TILE_BYTES,     Al, NC, k0, tid);
        load_tile_async(base + 2 * TILE_BYTES, Bf, NC, k0, tid);
    };

    load_chunk(0, 0);
    cp_commit();
    load_chunk(1, 1);
    cp_commit();

    int stage = 0;
    for (int ch = 0; ch < nch; ch++) {
        if (ch + 1 < nch) cp_wait<1>(); else cp_wait<0>();
        __syncthreads();
        if (ch + 2 < nch) {
            int ns = stage + 2;
            if (ns >= 3) ns -= 3;
            load_chunk(ch + 2, ns);
            cp_commit();
        }

        uint32_t base = sb + stage * F16_STAGE;
        if (++stage == 3) stage = 0;

        #pragma unroll
        for (int ks = 0; ks < 2; ks++) {
            uint32_t koff = (uint32_t)(ks * 32 + (lane >> 4) * 16);
            uint32_t ah[2][4], al[2][4];
            #pragma unroll
            for (int mt = 0; mt < 2; mt++) {
                uint32_t r = wm * 32 + mt * 16 + (lane & 15);
                uint32_t addr = base + r * ROW_BYTES + koff;
                ldm_x4(ah[mt], addr);
                ldm_x4(al[mt], addr + TILE_BYTES);
            }
            uint32_t bfr[4][4];
            #pragma unroll
            for (int ng = 0; ng < 4; ng++) {
                uint32_t r = wn * 64 + ng * 16 + (lane & 15);
                ldm_x4(bfr[ng], base + 2 * TILE_BYTES + r * ROW_BYTES + koff);
            }
            #pragma unroll
            for (int mt = 0; mt < 2; mt++)
                #pragma unroll
                for (int ng = 0; ng < 4; ng++) {
                    mma_f16(acc[mt][2 * ng],     ah[mt], bfr[ng][0], bfr[ng][2]);
                    mma_f16(acc[mt][2 * ng],     al[mt], bfr[ng][0], bfr[ng][2]);
                    mma_f16(acc[mt][2 * ng + 1], ah[mt], bfr[ng][1], bfr[ng][3]);
                    mma_f16(acc[mt][2 * ng + 1], al[mt], bfr[ng][1], bfr[ng][3]);
                }
        }
    }

    // fold bias into acc
    #pragma unroll
    for (int mt = 0; mt < 2; mt++)
        #pragma unroll
        for (int nt = 0; nt < 8; nt++) {
            int c = wn * 64 + nt * 8 + (lane & 3) * 2;
            float bx = bias[c], by = bias[c + 1];
            acc[mt][nt][0] += bx; acc[mt][nt][1] += by;
            acc[mt][nt][2] += bx; acc[mt][nt][3] += by;
        }

    if (MODE == 0) {
        float* Out = OutFG + bm * NC + bn;
        #pragma unroll
        for (int mt = 0; mt < 2; mt++) {
            int r0 = wm * 32 + mt * 16 + (lane >> 2);
            #pragma unroll
            for (int nt = 0; nt < 8; nt++) {
                int c = wn * 64 + nt * 8 + (lane & 3) * 2;
                float2 v0 = { acc[mt][nt][0], acc[mt][nt][1] };
                float2 v1 = { acc[mt][nt][2], acc[mt][nt][3] };
                *(float2*)(Out + (size_t)r0 * NC + c) = v0;
                *(float2*)(Out + (size_t)(r0 + 8) * NC + c) = v1;
            }
        }
    } else if (MODE == 3) {
        // fused transpose: stage f16 tile in smem, write V^T coalesced
        __syncthreads();                     // pipeline smem reads done
        f16* tv = (f16*)sm;                  // [128][TV_STRIDE]
        #pragma unroll
        for (int mt = 0; mt < 2; mt++) {
            int r0 = wm * 32 + mt * 16 + (lane >> 2);
            #pragma unroll
            for (int nt = 0; nt < 8; nt++) {
                int c = wn * 64 + nt * 8 + (lane & 3) * 2;
                *(__half2*)(tv + r0 * TV_STRIDE + c) =
                    __floats2half2_rn(acc[mt][nt][0], acc[mt][nt][1]);
                *(__half2*)(tv + (r0 + 8) * TV_STRIDE + c) =
                    __floats2half2_rn(acc[mt][nt][2], acc[mt][nt][3]);
            }
        }
        __syncthreads();
        int b = (int)(bm >> 11);             // bm / NS
        int s0 = (int)(bm & (NS - 1));
        int c = tid >> 1;                    // 0..127 output channel row
        int half = tid & 1;                  // 0/1: which 64 seq elems
        uint32_t buf[32];                    // 64 f16
        #pragma unroll
        for (int i = 0; i < 32; i++) {
            int s = half * 64 + 2 * i;
            __half2 v{ tv[(size_t)s * TV_STRIDE + c],
                       tv[(size_t)(s + 1) * TV_STRIDE + c] };
            buf[i] = *reinterpret_cast<uint32_t*>(&v);
        }
        f16* dst = OutHG + ((size_t)b * NC + bn + c) * NS + s0 + half * 64;
        #pragma unroll
        for (int i = 0; i < 8; i++)
            ((uint4*)dst)[i] = ((uint4*)buf)[i];
    } else {
        // fused per-head RMSNorm + RoPE (tile == one head)
        __syncthreads();                     // pipeline smem reads done
        float* sums = (float*)sm;            // [2][128]
        #pragma unroll
        for (int mt = 0; mt < 2; mt++) {
            float ss0 = 0.f, ss1 = 0.f;
            #pragma unroll
            for (int nt = 0; nt < 8; nt++) {
                ss0 += acc[mt][nt][0] * acc[mt][nt][0]
                     + acc[mt][nt][1] * acc[mt][nt][1];
                ss1 += acc[mt][nt][2] * acc[mt][nt][2]
                     + acc[mt][nt][3] * acc[mt][nt][3];
            }
            ss0 += __shfl_xor_sync(0xffffffffu, ss0, 1);
            ss0 += __shfl_xor_sync(0xffffffffu, ss0, 2);
            ss1 += __shfl_xor_sync(0xffffffffu, ss1, 1);
            ss1 += __shfl_xor_sync(0xffffffffu, ss1, 2);
            int r0 = wm * 32 + mt * 16 + (lane >> 2);
            if ((lane & 3) == 0) {
                sums[wn * 128 + r0] = ss0;
                sums[wn * 128 + r0 + 8] = ss1;
            }
        }
        __syncthreads();
        #pragma unroll
        for (int mt = 0; mt < 2; mt++) {
            int r0 = wm * 32 + mt * 16 + (lane >> 2);
            int m0 = (int)bm + r0, m1 = m0 + 8;
            int s0 = m0 & (NS - 1), s1 = m1 & (NS - 1);
            float rq0 = rsqrtf((sums[r0] + sums[128 + r0]) * (1.0f / ND) + RMS_EPS);
            float rq1 = rsqrtf((sums[r0 + 8] + sums[128 + r0 + 8]) * (1.0f / ND) + RMS_EPS);
            #pragma unroll
            for (int nt = 0; nt < 8; nt++) {
                int c = wn * 64 + nt * 8 + (lane & 3) * 2;
                float g0 = gamma[c], g1 = gamma[c + 1];
                float4 rp0 = *(const float4*)(rope + (size_t)s0 * 256 + c * 2);
                float4 rp1 = *(const float4*)(rope + (size_t)s1 * 256 + c * 2);
                float x0 = acc[mt][nt][0] * rq0 * g0;
                float x1 = acc[mt][nt][1] * rq0 * g1;
                float y0 = rp0.x * x0 + rp0.y * x1;
                float y1 = rp0.z * x0 + rp0.w * x1;
                float x2 = acc[mt][nt][2] * rq1 * g0;
                float x3 = acc[mt][nt][3] * rq1 * g1;
                float y2 = rp1.x * x2 + rp1.y * x3;
                float y3 = rp1.z * x2 + rp1.w * x3;
                size_t o0 = (size_t)m0 * NC + bn + c;
                size_t o1 = (size_t)m1 * NC + bn + c;
                if (MODE == 1) {
                    f16 h0, l0, h1, l1;
                    split2f(y0, h0, l0); split2f(y1, h1, l1);
                    *(__half2*)(OutHG + o0) = __half2{h0, h1};
                    *(__half2*)(OutLG + o0) = __half2{l0, l1};
                    split2f(y2, h0, l0); split2f(y3, h1, l1);
                    *(__half2*)(OutHG + o1) = __half2{h0, h1};
                    *(__half2*)(OutLG + o1) = __half2{l0, l1};
                } else {
                    *(__half2*)(OutHG + o0) = __floats2half2_rn(y0, y1);
                    *(__half2*)(OutHG + o1) = __floats2half2_rn(y2, y3);
                }
            }
        }
    }
}

// =========================================================================
// Flash attention: scores (f16 2-term) + online softmax + PV (f16 1-term)
// Double-buffered K AND V (unchanged from R11).
// =========================================================================
#define FT_ROWB 272                          // 256B row + 16B pad
#define FT_TILE (128 * FT_ROWB)              // 34816
#define OFF_K 0
#define OFF_V (2 * FT_TILE)
#define FLASH_SMEM (4 * FT_TILE)             // 139264

__device__ __forceinline__ void fa_load_one(uint32_t dst, const f16* g,
                                            size_t rowbase, size_t ldrow, int tid)
{
    #pragma unroll
    for (int i = 0; i < 8; i++) {
        int idx = tid + i * 256;
        int row = idx >> 4;
        int ch = idx & 15;
        cp_async16(dst + row * FT_ROWB + ch * 16,
                   (const char*)(g + rowbase + (size_t)row * ldrow) + ch * 16);
    }
}

__global__ void __launch_bounds__(256, 1) k_flash()
{
    extern __shared__ char sm[];
    uint32_t sb = smem_to_u32(sm);
    const int tid = threadIdx.x;
    const int lane = tid & 31;
    const int warp = tid >> 5;
    const int q0 = blockIdx.x * 128;
    const int bh = blockIdx.y, b = bh >> 4, h = bh & 15;

    const size_t kbase = (size_t)(b * NS) * NC + (size_t)h * ND;
    const size_t vbase = ((size_t)b * NC + (size_t)h * ND) * NS;

    size_t qbase = (size_t)(b * NS + q0) * NC + (size_t)h * ND;
    fa_load_one(sb + OFF_K, g_qhf, qbase, NC, tid);
    fa_load_one(sb + OFF_V, g_qlf, qbase, NC, tid);
    cp_commit();                                        // group: Q
    fa_load_one(sb + OFF_K + FT_TILE, g_kf, kbase, NC, tid);
    fa_load_one(sb + OFF_V + FT_TILE, g_vtf, vbase, NS, tid);
    cp_commit();                                        // group: K0,V0
    cp_wait<1>();                                       // Q ready
    __syncthreads();

    uint32_t qhf[8][4], qlf[8][4];
    {
        uint32_t rbase = sb + (warp * 16 + (lane & 15)) * FT_ROWB + ((lane >> 4) << 4);
        #pragma unroll
        for (int ks = 0; ks < 8; ks++) {
            ldm_x4(qhf[ks], rbase + OFF_K + ks * 32);
            ldm_x4(qlf[ks], rbase + OFF_V + ks * 32);
        }
    }
    __syncthreads();                                    // Q buffers free

    fa_load_one(sb + OFF_K, g_kf, kbase + (size_t)128 * NC, NC, tid);
    fa_load_one(sb + OFF_V, g_vtf, vbase + 128, NS, tid);
    cp_commit();                                        // group: K1,V1

    float o[16][4];
    #pragma unroll
    for (int i = 0; i < 16; i++) { o[i][0] = 0.f; o[i][1] = 0.f; o[i][2] = 0.f; o[i][3] = 0.f; }
    float m0 = -1e30f, m1 = -1e30f, l0 = 0.f, l1 = 0.f;

    for (int j = 0; j < 16; j++) {
        if (j + 1 < 16) cp_wait<1>(); else cp_wait<0>();
        __syncthreads();

        uint32_t bufo = (uint32_t)((j + 1) & 1) * FT_TILE;

        float s[16][4];
        #pragma unroll
        for (int i = 0; i < 16; i++) { s[i][0] = 0.f; s[i][1] = 0.f; s[i][2] = 0.f; s[i][3] = 0.f; }
        #pragma unroll
        for (int ng = 0; ng < 8; ng++) {
            #pragma unroll
            for (int ks = 0; ks < 8; ks++) {
                uint32_t addr = sb + OFF_K + bufo + (ng * 16 + (lane & 15)) * FT_ROWB
                              + ((lane >> 4) << 4) + ks * 32;
                uint32_t kf4[4];
                ldm_x4(kf4, addr);
                mma_f16(s[2 * ng],     qhf[ks], kf4[0], kf4[2]);
                mma_f16(s[2 * ng],     qlf[ks], kf4[0], kf4[2]);
                mma_f16(s[2 * ng + 1], qhf[ks], kf4[1], kf4[3]);
                mma_f16(s[2 * ng + 1], qlf[ks], kf4[1], kf4[3]);
            }
        }

        float mx0 = -1e30f, mx1 = -1e30f;
        #pragma unroll
        for (int i = 0; i < 16; i++) {
            mx0 = fmaxf(mx0, fmaxf(s[i][0], s[i][1]));
            mx1 = fmaxf(mx1, fmaxf(s[i][2], s[i][3]));
        }
        mx0 = fmaxf(mx0, __shfl_xor_sync(0xffffffffu, mx0, 1));
        mx0 = fmaxf(mx0, __shfl_xor_sync(0xffffffffu, mx0, 2));
        mx1 = fmaxf(mx1, __shfl_xor_sync(0xffffffffu, mx1, 1));
        mx1 = fmaxf(mx1, __shfl_xor_sync(0xffffffffu, mx1, 2));
        float nm0 = fmaxf(m0, mx0), nm1 = fmaxf(m1, mx1);
        float a0 = __expf((m0 - nm0) * SM_SCALE);
        float a1 = __expf((m1 - nm1) * SM_SCALE);
        m0 = nm0; m1 = nm1;
        float ps0 = 0.f, ps1 = 0.f;
        #pragma unroll
        for (int i = 0; i < 16; i++) {
            s[i][0] = __expf((s[i][0] - m0) * SM_SCALE);
            s[i][1] = __expf((s[i][1] - m0) * SM_SCALE);
            s[i][2] = __expf((s[i][2] - m1) * SM_SCALE);
            s[i][3] = __expf((s[i][3] - m1) * SM_SCALE);
            ps0 += s[i][0] + s[i][1];
            ps1 += s[i][2] + s[i][3];
        }
        l0 = l0 * a0 + ps0;
        l1 = l1 * a1 + ps1;
        #pragma unroll
        for (int i = 0; i < 16; i++) {
            o[i][0] *= a0; o[i][1] *= a0; o[i][2] *= a1; o[i][3] *= a1;
        }

        #pragma unroll
        for (int ks = 0; ks < 8; ks++) {
            uint32_t pa[4];
            pa[0] = pack_f16x2(s[2 * ks][0],     s[2 * ks][1]);
            pa[1] = pack_f16x2(s[2 * ks][2],     s[2 * ks][3]);
            pa[2] = pack_f16x2(s[2 * ks + 1][0], s[2 * ks + 1][1]);
            pa[3] = pack_f16x2(s[2 * ks + 1][2], s[2 * ks + 1][3]);
            #pragma unroll
            for (int ng = 0; ng < 8; ng++) {
                uint32_t addr = sb + OFF_V + bufo + (ng * 16 + (lane & 15)) * FT_ROWB
                              + ((lane >> 4) << 4) + ks * 32;
                uint32_t vf4[4];
                ldm_x4(vf4, addr);
                mma_f16(o[2 * ng],     pa, vf4[0], vf4[2]);
                mma_f16(o[2 * ng + 1], pa, vf4[1], vf4[3]);
            }
        }

        __syncthreads();
        if (j + 2 < 16) {
            fa_load_one(sb + OFF_K + bufo, g_kf,
                        kbase + (size_t)(j + 2) * 128 * NC, NC, tid);
            fa_load_one(sb + OFF_V + bufo, g_vtf,
                        vbase + (size_t)(j + 2) * 128, NS, tid);
            cp_commit();
        }
    }

    l0 += __shfl_xor_sync(0xffffffffu, l0, 1);
    l0 += __shfl_xor_sync(0xffffffffu, l0, 2);
    l1 += __shfl_xor_sync(0xffffffffu, l1, 1);
    l1 += __shfl_xor_sync(0xffffffffu, l1, 2);
    float i0 = 1.0f / l0, i1 = 1.0f / l1;

    size_t gr0 = (size_t)(b * NS + q0 + warp * 16 + (lane >> 2));
    #pragma unroll
    for (int nt = 0; nt < 16; nt++) {
        int c = h * ND + nt * 8 + (lane & 3) * 2;
        f16 h0, h1, lo0, lo1;
        split2f(o[nt][0] * i0, h0, lo0);
        split2f(o[nt][1] * i0, h1, lo1);
        *(__half2*)(g_chf + gr0 * NC + c) = __half2{h0, h1};
        *(__half2*)(g_clf + gr0 * NC + c) = __half2{lo0, lo1};
        split2f(o[nt][2] * i1, h0, lo0);
        split2f(o[nt][3] * i1, h1, lo1);
        *(__half2*)(g_chf + (gr0 + 8) * NC + c) = __half2{h0, h1};
        *(__half2*)(g_clf + (gr0 + 8) * NC + c) = __half2{lo0, lo1};
    }
}

// ---------------- elementwise kernels ----------------
__global__ __launch_bounds__(256) void cvt_split_f16(const float* __restrict__ src,
                                                     f16* __restrict__ hi,
                                                     f16* __restrict__ lo)
{
    size_t i = (size_t)blockIdx.x * 256 + threadIdx.x;
    float4 v = ((const float4*)src)[i];
    f16 h0, h1, h2, h3, l0, l1, l2, l3;
    split2f(v.x, h0, l0); split2f(v.y, h1, l1);
    split2f(v.z, h2, l2); split2f(v.w, h3, l3);
    __half2* hp = (__half2*)hi;
    __half2* lp = (__half2*)lo;
    hp[2 * i]     = __half2{h0, h1};
    hp[2 * i + 1] = __half2{h2, h3};
    lp[2 * i]     = __half2{l0, l1};
    lp[2 * i + 1] = __half2{l2, l3};
}

// Convert the 4 weight matrices in one launch: blockIdx.y selects tensor.
__global__ __launch_bounds__(256) void cvt_f16_w(
    const float* __restrict__ s0, const float* __restrict__ s1,
    const float* __restrict__ s2, const float* __restrict__ s3,
    f16* __restrict__ d0, f16* __restrict__ d1,
    f16* __restrict__ d2, f16* __restrict__ d3)
{
    const float* src = (blockIdx.y == 0) ? s0 : (blockIdx.y == 1) ? s1
                     : (blockIdx.y == 2) ? s2 : s3;
    f16* dst = (blockIdx.y == 0) ? d0 : (blockIdx.y == 1) ? d1
             : (blockIdx.y == 2) ? d2 : d3;
    size_t i = (size_t)blockIdx.x * 256 + threadIdx.x;
    float4 v = ((const float4*)src)[i];
    __half2* dp = (__half2*)dst;
    dp[2 * i]     = __floats2half2_rn(v.x, v.y);
    dp[2 * i + 1] = __floats2half2_rn(v.z, v.w);
}

// ---------------- launch ----------------
extern "C" void kernel_launch(void* const* d_in, const int* in_sizes, int n_in,
                              void* d_out, int out_size)
{
    const float* x    = (const float*)d_in[0];
    const float* rope = (const float*)d_in[1];
    const float* Wq   = (const float*)d_in[2];
    const float* bq   = (const float*)d_in[3];
    const float* Wk   = (const float*)d_in[4];
    const float* bk   = (const float*)d_in[5];
    const float* Wv   = (const float*)d_in[6];
    const float* bv   = (const float*)d_in[7];
    const float* gq   = (const float*)d_in[8];
    const float* gk   = (const float*)d_in[9];
    const float* Wo   = (const float*)d_in[10];
    const float* bo   = (const float*)d_in[11];
    float* out = (float*)d_out;

    cudaFuncSetAttribute(k_gemm_f16<0>, cudaFuncAttributeMaxDynamicSharedMemorySize, F16_SMEM);
    cudaFuncSetAttribute(k_gemm_f16<1>, cudaFuncAttributeMaxDynamicSharedMemorySize, F16_SMEM);
    cudaFuncSetAttribute(k_gemm_f16<2>, cudaFuncAttributeMaxDynamicSharedMemorySize, F16_SMEM);
    cudaFuncSetAttribute(k_gemm_f16<3>, cudaFuncAttributeMaxDynamicSharedMemorySize, F16_SMEM);
    cudaFuncSetAttribute(k_flash, cudaFuncAttributeMaxDynamicSharedMemorySize, FLASH_SMEM);

    f16 *xhf, *xlf, *wqf, *wkf, *wvf, *wof, *chf, *clf, *qhf, *qlf, *kf, *vtf;
    cudaGetSymbolAddress((void**)&xhf, g_xhf); cudaGetSymbolAddress((void**)&xlf, g_xlf);
    cudaGetSymbolAddress((void**)&wqf, g_wqf); cudaGetSymbolAddress((void**)&wkf, g_wkf);
    cudaGetSymbolAddress((void**)&wvf, g_wvf); cudaGetSymbolAddress((void**)&wof, g_wof);
    cudaGetSymbolAddress((void**)&chf, g_chf); cudaGetSymbolAddress((void**)&clf, g_clf);
    cudaGetSymbolAddress((void**)&qhf, g_qhf); cudaGetSymbolAddress((void**)&qlf, g_qlf);
    cudaGetSymbolAddress((void**)&kf, g_kf);   cudaGetSymbolAddress((void**)&vtf, g_vtf);

    const size_t nX = (size_t)NM * NC;       // 8M elems
    const size_t nW = (size_t)NC * NC;       // 4M elems

    cvt_split_f16<<<(unsigned)(nX / 1024), 256>>>(x, xhf, xlf);
    cvt_f16_w<<<dim3((unsigned)(nW / 1024), 4), 256>>>(Wq, Wk, Wv, Wo,
                                                       wqf, wkf, wvf, wof);

    dim3 gProj(NC / 128, NM / 128);          // (16, 32)
    // Q: fused RMSNorm+RoPE -> split f16
    k_gemm_f16<1><<<gProj, 256, F16_SMEM>>>(xhf, xlf, wqf, bq,
                                            nullptr, qhf, qlf, rope, gq);
    // K: fused RMSNorm+RoPE -> single f16
    k_gemm_f16<2><<<gProj, 256, F16_SMEM>>>(xhf, xlf, wkf, bk,
                                            nullptr, kf, nullptr, rope, gk);
    // V: fused transpose -> f16 V^T
    k_gemm_f16<3><<<gProj, 256, F16_SMEM>>>(xhf, xlf, wvf, bv,
                                            nullptr, vtf, nullptr, nullptr, nullptr);

    k_flash<<<dim3(NS / 128, NBH), 256, FLASH_SMEM>>>();

    // out-proj: plain fp32 to harness output
    k_gemm_f16<0><<<gProj, 256, F16_SMEM>>>(chf, clf, wof, bo,
                                            out, nullptr, nullptr, nullptr, nullptr);
}

// round 17
// speedup vs baseline: 1.2215x; 1.0781x over previous
#include <cuda_runtime.h>
#include <cuda_bf16.h>
#include <cuda_fp16.h>
#include <math.h>
#include <stdint.h>
#include <stddef.h>

#define NB 2
#define NS 2048
#define NC 2048
#define ND 128
#define NH 16
#define NM (NB * NS)       // 4096
#define NBH (NB * NH)      // 32
#define RMS_EPS 1.1920928955078125e-07f
#define SM_SCALE 0.08838834764831844f

typedef __half f16;

// ---------------- scratch (device globals; no allocation) ----------------
__device__ f16 g_xhf[(size_t)NM * NC], g_xlf[(size_t)NM * NC];
__device__ f16 g_wqf[(size_t)NC * NC], g_wkf[(size_t)NC * NC];
__device__ f16 g_wvf[(size_t)NC * NC], g_wof[(size_t)NC * NC];
__device__ f16 g_vtf[(size_t)NB * NC * NS];
__device__ f16 g_chf[(size_t)NM * NC], g_clf[(size_t)NM * NC];
__device__ f16 g_qhf[(size_t)NM * NC], g_qlf[(size_t)NM * NC];   // Q split 2xf16
__device__ f16 g_kf[(size_t)NM * NC];                            // K single f16

// ---------------- PTX helpers (sm_80-era, family-target safe) -------------
__device__ __forceinline__ uint32_t smem_to_u32(const void* p) {
    uint32_t a;
    asm("{ .reg .u64 t; cvta.to.shared.u64 t, %1; cvt.u32.u64 %0, t; }"
        : "=r"(a) : "l"(p));
    return a;
}
__device__ __forceinline__ void cp_async16(uint32_t dst, const void* src) {
    asm volatile("cp.async.cg.shared.global [%0], [%1], 16;"
                 :: "r"(dst), "l"(src) : "memory");
}
__device__ __forceinline__ void cp_commit() {
    asm volatile("cp.async.commit_group;" ::: "memory");
}
template <int N>
__device__ __forceinline__ void cp_wait() {
    asm volatile("cp.async.wait_group %0;" :: "n"(N) : "memory");
}
__device__ __forceinline__ void ldm_x4(uint32_t (&r)[4], uint32_t addr) {
    asm volatile("ldmatrix.sync.aligned.m8n8.x4.shared.b16 {%0,%1,%2,%3}, [%4];"
                 : "=r"(r[0]), "=r"(r[1]), "=r"(r[2]), "=r"(r[3]) : "r"(addr));
}
__device__ __forceinline__ void mma_f16(float (&d)[4], const uint32_t (&a)[4],
                                        uint32_t b0, uint32_t b1) {
    asm volatile("mma.sync.aligned.m16n8k16.row.col.f32.f16.f16.f32 "
                 "{%0,%1,%2,%3}, {%4,%5,%6,%7}, {%8,%9}, {%0,%1,%2,%3};"
                 : "+f"(d[0]), "+f"(d[1]), "+f"(d[2]), "+f"(d[3])
                 : "r"(a[0]), "r"(a[1]), "r"(a[2]), "r"(a[3]), "r"(b0), "r"(b1));
}

__device__ __forceinline__ void split2f(float x, f16& h, f16& l) {
    h = __float2half_rn(x);
    l = __float2half_rn(x - __half2float(h));
}
__device__ __forceinline__ uint32_t pack_f16x2(float x, float y) {
    __half2 H = __floats2half2_rn(x, y);
    return *reinterpret_cast<uint32_t*>(&H);
}

// ---------------- common tiling constants ----------------
#define KCH 32
#define ROW_BYTES 80
#define TILE_BYTES (128 * ROW_BYTES)        // 10240

__device__ __forceinline__ void load_tile_async(uint32_t smbase, const void* g,
                                                int ld, int k0, int tid) {
    const char* gp = (const char*)g + (size_t)k0 * 2;
    #pragma unroll
    for (int j = 0; j < 2; j++) {
        int i = tid + j * 256;
        int row = i >> 2;
        int c = i & 3;
        cp_async16(smbase + row * ROW_BYTES + c * 16,
                   gp + (size_t)row * ld * 2 + c * 16);
    }
}

#define F16_STAGE (3 * TILE_BYTES)          // 30720
#define F16_SMEM (3 * F16_STAGE)            // 92160
#define TV_STRIDE 130                        // f16 units; conflict-light

// =========================================================================
// GEMM mainloop shared by both kernels (R11 tiling; 3-stage pipeline).
// Computes acc[2][8][4] for the (bm, bn) tile with bias folded in.
// =========================================================================
__device__ __forceinline__ void gemm_mainloop(
    const f16* __restrict__ Ah, const f16* __restrict__ Al,
    const f16* __restrict__ Bf, const float* __restrict__ bias,
    uint32_t sb, int tid, int lane, int wm, int wn,
    float (&acc)[2][8][4])
{
    #pragma unroll
    for (int mt = 0; mt < 2; mt++)
        #pragma unroll
        for (int nt = 0; nt < 8; nt++)
            #pragma unroll
            for (int j = 0; j < 4; j++) acc[mt][nt][j] = 0.0f;

    const int nch = NC / KCH;

    auto load_chunk = [&](int ch, int s) {
        uint32_t base = sb + s * F16_STAGE;
        int k0 = ch * KCH;
        load_tile_async(base,                  Ah, NC, k0, tid);
        load_tile_async(base + TILE_BYTES,     Al, NC, k0, tid);
        load_tile_async(base + 2 * TILE_BYTES, Bf, NC, k0, tid);
    };

    load_chunk(0, 0);
    cp_commit();
    load_chunk(1, 1);
    cp_commit();

    int stage = 0;
    for (int ch = 0; ch < nch; ch++) {
        if (ch + 1 < nch) cp_wait<1>(); else cp_wait<0>();
        __syncthreads();
        if (ch + 2 < nch) {
            int ns = stage + 2;
            if (ns >= 3) ns -= 3;
            load_chunk(ch + 2, ns);
            cp_commit();
        }

        uint32_t base = sb + stage * F16_STAGE;
        if (++stage == 3) stage = 0;

        #pragma unroll
        for (int ks = 0; ks < 2; ks++) {
            uint32_t koff = (uint32_t)(ks * 32 + (lane >> 4) * 16);
            uint32_t ah[2][4], al[2][4];
            #pragma unroll
            for (int mt = 0; mt < 2; mt++) {
                uint32_t r = wm * 32 + mt * 16 + (lane & 15);
                uint32_t addr = base + r * ROW_BYTES + koff;
                ldm_x4(ah[mt], addr);
                ldm_x4(al[mt], addr + TILE_BYTES);
            }
            uint32_t bfr[4][4];
            #pragma unroll
            for (int ng = 0; ng < 4; ng++) {
                uint32_t r = wn * 64 + ng * 16 + (lane & 15);
                ldm_x4(bfr[ng], base + 2 * TILE_BYTES + r * ROW_BYTES + koff);
            }
            #pragma unroll
            for (int mt = 0; mt < 2; mt++)
                #pragma unroll
                for (int ng = 0; ng < 4; ng++) {
                    mma_f16(acc[mt][2 * ng],     ah[mt], bfr[ng][0], bfr[ng][2]);
                    mma_f16(acc[mt][2 * ng],     al[mt], bfr[ng][0], bfr[ng][2]);
                    mma_f16(acc[mt][2 * ng + 1], ah[mt], bfr[ng][1], bfr[ng][3]);
                    mma_f16(acc[mt][2 * ng + 1], al[mt], bfr[ng][1], bfr[ng][3]);
                }
        }
    }

    // fold bias
    #pragma unroll
    for (int mt = 0; mt < 2; mt++)
        #pragma unroll
        for (int nt = 0; nt < 8; nt++) {
            int c = wn * 64 + nt * 8 + (lane & 3) * 2;
            float bx = bias[c], by = bias[c + 1];
            acc[mt][nt][0] += bx; acc[mt][nt][1] += by;
            acc[mt][nt][2] += bx; acc[mt][nt][3] += by;
        }
}

// =========================================================================
// Fused QKV GEMM: ONE launch, grid.z selects operand (0=Q, 1=K, 2=V) so
// the CLC work-steals across what were 3 kernel-boundary tails.
//   z=0 (Q): bias + per-head RMSNorm + RoPE -> split f16 (qh/ql)
//   z=1 (K): bias + per-head RMSNorm + RoPE -> single f16 (kf)
//   z=2 (V): bias + transpose -> f16 V^T (vtf), via smem staging
// =========================================================================
__global__ __launch_bounds__(256, 2)
void k_gemm_qkv(const f16* __restrict__ AhG, const f16* __restrict__ AlG,
                const f16* __restrict__ Wq, const f16* __restrict__ Wk,
                const f16* __restrict__ Wv,
                const float* __restrict__ bq, const float* __restrict__ bk,
                const float* __restrict__ bv,
                f16* __restrict__ qh, f16* __restrict__ ql,
                f16* __restrict__ kfo, f16* __restrict__ vtf,
                const float* __restrict__ rope,
                const float* __restrict__ gq, const float* __restrict__ gk)
{
    const int mode = blockIdx.z;             // 0=Q, 1=K, 2=V
    size_t bm = (size_t)blockIdx.y * 128;
    size_t bn = (size_t)blockIdx.x * 128;
    const f16* Bf = (mode == 0) ? Wq : (mode == 1) ? Wk : Wv;
    const float* biasG = (mode == 0) ? bq : (mode == 1) ? bk : bv;

    extern __shared__ char sm[];
    uint32_t sb = smem_to_u32(sm);
    const int tid = threadIdx.x;
    const int lane = tid & 31;
    const int warp = tid >> 5;
    const int wm = warp >> 1;
    const int wn = warp & 1;

    float acc[2][8][4];
    gemm_mainloop(AhG + bm * NC, AlG + bm * NC, Bf + bn * NC, biasG + bn,
                  sb, tid, lane, wm, wn, acc);

    if (mode == 2) {
        // fused transpose: stage f16 tile in smem, write V^T coalesced
        __syncthreads();
        f16* tv = (f16*)sm;                  // [128][TV_STRIDE]
        #pragma unroll
        for (int mt = 0; mt < 2; mt++) {
            int r0 = wm * 32 + mt * 16 + (lane >> 2);
            #pragma unroll
            for (int nt = 0; nt < 8; nt++) {
                int c = wn * 64 + nt * 8 + (lane & 3) * 2;
                *(__half2*)(tv + r0 * TV_STRIDE + c) =
                    __floats2half2_rn(acc[mt][nt][0], acc[mt][nt][1]);
                *(__half2*)(tv + (r0 + 8) * TV_STRIDE + c) =
                    __floats2half2_rn(acc[mt][nt][2], acc[mt][nt][3]);
            }
        }
        __syncthreads();
        int b = (int)(bm >> 11);
        int s0 = (int)(bm & (NS - 1));
        int c = tid >> 1;
        int half = tid & 1;
        uint32_t buf[32];
        #pragma unroll
        for (int i = 0; i < 32; i++) {
            int s = half * 64 + 2 * i;
            __half2 v{ tv[(size_t)s * TV_STRIDE + c],
                       tv[(size_t)(s + 1) * TV_STRIDE + c] };
            buf[i] = *reinterpret_cast<uint32_t*>(&v);
        }
        f16* dst = vtf + ((size_t)b * NC + bn + c) * NS + s0 + half * 64;
        #pragma unroll
        for (int i = 0; i < 8; i++)
            ((uint4*)dst)[i] = ((uint4*)buf)[i];
    } else {
        // fused per-head RMSNorm + RoPE (tile == one head)
        const float* gamma = (mode == 0) ? gq : gk;
        __syncthreads();
        float* sums = (float*)sm;            // [2][128]
        #pragma unroll
        for (int mt = 0; mt < 2; mt++) {
            float ss0 = 0.f, ss1 = 0.f;
            #pragma unroll
            for (int nt = 0; nt < 8; nt++) {
                ss0 += acc[mt][nt][0] * acc[mt][nt][0]
                     + acc[mt][nt][1] * acc[mt][nt][1];
                ss1 += acc[mt][nt][2] * acc[mt][nt][2]
                     + acc[mt][nt][3] * acc[mt][nt][3];
            }
            ss0 += __shfl_xor_sync(0xffffffffu, ss0, 1);
            ss0 += __shfl_xor_sync(0xffffffffu, ss0, 2);
            ss1 += __shfl_xor_sync(0xffffffffu, ss1, 1);
            ss1 += __shfl_xor_sync(0xffffffffu, ss1, 2);
            int r0 = wm * 32 + mt * 16 + (lane >> 2);
            if ((lane & 3) == 0) {
                sums[wn * 128 + r0] = ss0;
                sums[wn * 128 + r0 + 8] = ss1;
            }
        }
        __syncthreads();
        #pragma unroll
        for (int mt = 0; mt < 2; mt++) {
            int r0 = wm * 32 + mt * 16 + (lane >> 2);
            int m0 = (int)bm + r0, m1 = m0 + 8;
            int s0 = m0 & (NS - 1), s1 = m1 & (NS - 1);
            float rq0 = rsqrtf((sums[r0] + sums[128 + r0]) * (1.0f / ND) + RMS_EPS);
            float rq1 = rsqrtf((sums[r0 + 8] + sums[128 + r0 + 8]) * (1.0f / ND) + RMS_EPS);
            #pragma unroll
            for (int nt = 0; nt < 8; nt++) {
                int c = wn * 64 + nt * 8 + (lane & 3) * 2;
                float g0 = gamma[c], g1 = gamma[c + 1];
                float4 rp0 = *(const float4*)(rope + (size_t)s0 * 256 + c * 2);
                float4 rp1 = *(const float4*)(rope + (size_t)s1 * 256 + c * 2);
                float x0 = acc[mt][nt][0] * rq0 * g0;
                float x1 = acc[mt][nt][1] * rq0 * g1;
                float y0 = rp0.x * x0 + rp0.y * x1;
                float y1 = rp0.z * x0 + rp0.w * x1;
                float x2 = acc[mt][nt][2] * rq1 * g0;
                float x3 = acc[mt][nt][3] * rq1 * g1;
                float y2 = rp1.x * x2 + rp1.y * x3;
                float y3 = rp1.z * x2 + rp1.w * x3;
                size_t o0 = (size_t)m0 * NC + bn + c;
                size_t o1 = (size_t)m1 * NC + bn + c;
                if (mode == 0) {
                    f16 h0, l0, h1, l1;
                    split2f(y0, h0, l0); split2f(y1, h1, l1);
                    *(__half2*)(qh + o0) = __half2{h0, h1};
                    *(__half2*)(ql + o0) = __half2{l0, l1};
                    split2f(y2, h0, l0); split2f(y3, h1, l1);
                    *(__half2*)(qh + o1) = __half2{h0, h1};
                    *(__half2*)(ql + o1) = __half2{l0, l1};
                } else {
                    *(__half2*)(kfo + o0) = __floats2half2_rn(y0, y1);
                    *(__half2*)(kfo + o1) = __floats2half2_rn(y2, y3);
                }
            }
        }
    }
}

// out-proj: plain fp32 + bias
__global__ __launch_bounds__(256, 2)
void k_gemm_out(const f16* __restrict__ AhG, const f16* __restrict__ AlG,
                const f16* __restrict__ BfG, const float* __restrict__ biasG,
                float* __restrict__ OutG)
{
    size_t bm = (size_t)blockIdx.y * 128;
    size_t bn = (size_t)blockIdx.x * 128;
    extern __shared__ char sm[];
    uint32_t sb = smem_to_u32(sm);
    const int tid = threadIdx.x;
    const int lane = tid & 31;
    const int warp = tid >> 5;
    const int wm = warp >> 1;
    const int wn = warp & 1;

    float acc[2][8][4];
    gemm_mainloop(AhG + bm * NC, AlG + bm * NC, BfG + bn * NC, biasG + bn,
                  sb, tid, lane, wm, wn, acc);

    float* Out = OutG + bm * NC + bn;
    #pragma unroll
    for (int mt = 0; mt < 2; mt++) {
        int r0 = wm * 32 + mt * 16 + (lane >> 2);
        #pragma unroll
        for (int nt = 0; nt < 8; nt++) {
            int c = wn * 64 + nt * 8 + (lane & 3) * 2;
            float2 v0 = { acc[mt][nt][0], acc[mt][nt][1] };
            float2 v1 = { acc[mt][nt][2], acc[mt][nt][3] };
            *(float2*)(Out + (size_t)r0 * NC + c) = v0;
            *(float2*)(Out + (size_t)(r0 + 8) * NC + c) = v1;
        }
    }
}

// =========================================================================
// Flash attention: scores (f16 2-term) + online softmax + PV (f16 1-term)
// Double-buffered K AND V (unchanged).
// =========================================================================
#define FT_ROWB 272                          // 256B row + 16B pad
#define FT_TILE (128 * FT_ROWB)              // 34816
#define OFF_K 0
#define OFF_V (2 * FT_TILE)
#define FLASH_SMEM (4 * FT_TILE)             // 139264

__device__ __forceinline__ void fa_load_one(uint32_t dst, const f16* g,
                                            size_t rowbase, size_t ldrow, int tid)
{
    #pragma unroll
    for (int i = 0; i < 8; i++) {
        int idx = tid + i * 256;
        int row = idx >> 4;
        int ch = idx & 15;
        cp_async16(dst + row * FT_ROWB + ch * 16,
                   (const char*)(g + rowbase + (size_t)row * ldrow) + ch * 16);
    }
}

__global__ void __launch_bounds__(256, 1) k_flash()
{
    extern __shared__ char sm[];
    uint32_t sb = smem_to_u32(sm);
    const int tid = threadIdx.x;
    const int lane = tid & 31;
    const int warp = tid >> 5;
    const int q0 = blockIdx.x * 128;
    const int bh = blockIdx.y, b = bh >> 4, h = bh & 15;

    const size_t kbase = (size_t)(b * NS) * NC + (size_t)h * ND;
    const size_t vbase = ((size_t)b * NC + (size_t)h * ND) * NS;

    size_t qbase = (size_t)(b * NS + q0) * NC + (size_t)h * ND;
    fa_load_one(sb + OFF_K, g_qhf, qbase, NC, tid);
    fa_load_one(sb + OFF_V, g_qlf, qbase, NC, tid);
    cp_commit();                                        // group: Q
    fa_load_one(sb + OFF_K + FT_TILE, g_kf, kbase, NC, tid);
    fa_load_one(sb + OFF_V + FT_TILE, g_vtf, vbase, NS, tid);
    cp_commit();                                        // group: K0,V0
    cp_wait<1>();                                       // Q ready
    __syncthreads();

    uint32_t qhf[8][4], qlf[8][4];
    {
        uint32_t rbase = sb + (warp * 16 + (lane & 15)) * FT_ROWB + ((lane >> 4) << 4);
        #pragma unroll
        for (int ks = 0; ks < 8; ks++) {
            ldm_x4(qhf[ks], rbase + OFF_K + ks * 32);
            ldm_x4(qlf[ks], rbase + OFF_V + ks * 32);
        }
    }
    __syncthreads();                                    // Q buffers free

    fa_load_one(sb + OFF_K, g_kf, kbase + (size_t)128 * NC, NC, tid);
    fa_load_one(sb + OFF_V, g_vtf, vbase + 128, NS, tid);
    cp_commit();                                        // group: K1,V1

    float o[16][4];
    #pragma unroll
    for (int i = 0; i < 16; i++) { o[i][0] = 0.f; o[i][1] = 0.f; o[i][2] = 0.f; o[i][3] = 0.f; }
    float m0 = -1e30f, m1 = -1e30f, l0 = 0.f, l1 = 0.f;

    for (int j = 0; j < 16; j++) {
        if (j + 1 < 16) cp_wait<1>(); else cp_wait<0>();
        __syncthreads();

        uint32_t bufo = (uint32_t)((j + 1) & 1) * FT_TILE;

        float s[16][4];
        #pragma unroll
        for (int i = 0; i < 16; i++) { s[i][0] = 0.f; s[i][1] = 0.f; s[i][2] = 0.f; s[i][3] = 0.f; }
        #pragma unroll
        for (int ng = 0; ng < 8; ng++) {
            #pragma unroll
            for (int ks = 0; ks < 8; ks++) {
                uint32_t addr = sb + OFF_K + bufo + (ng * 16 + (lane & 15)) * FT_ROWB
                              + ((lane >> 4) << 4) + ks * 32;
                uint32_t kf4[4];
                ldm_x4(kf4, addr);
                mma_f16(s[2 * ng],     qhf[ks], kf4[0], kf4[2]);
                mma_f16(s[2 * ng],     qlf[ks], kf4[0], kf4[2]);
                mma_f16(s[2 * ng + 1], qhf[ks], kf4[1], kf4[3]);
                mma_f16(s[2 * ng + 1], qlf[ks], kf4[1], kf4[3]);
            }
        }

        float mx0 = -1e30f, mx1 = -1e30f;
        #pragma unroll
        for (int i = 0; i < 16; i++) {
            mx0 = fmaxf(mx0, fmaxf(s[i][0], s[i][1]));
            mx1 = fmaxf(mx1, fmaxf(s[i][2], s[i][3]));
        }
        mx0 = fmaxf(mx0, __shfl_xor_sync(0xffffffffu, mx0, 1));
        mx0 = fmaxf(mx0, __shfl_xor_sync(0xffffffffu, mx0, 2));
        mx1 = fmaxf(mx1, __shfl_xor_sync(0xffffffffu, mx1, 1));
        mx1 = fmaxf(mx1, __shfl_xor_sync(0xffffffffu, mx1, 2));
        float nm0 = fmaxf(m0, mx0), nm1 = fmaxf(m1, mx1);
        float a0 = __expf((m0 - nm0) * SM_SCALE);
        float a1 = __expf((m1 - nm1) * SM_SCALE);
        m0 = nm0; m1 = nm1;
        float ps0 = 0.f, ps1 = 0.f;
        #pragma unroll
        for (int i = 0; i < 16; i++) {
            s[i][0] = __expf((s[i][0] - m0) * SM_SCALE);
            s[i][1] = __expf((s[i][1] - m0) * SM_SCALE);
            s[i][2] = __expf((s[i][2] - m1) * SM_SCALE);
            s[i][3] = __expf((s[i][3] - m1) * SM_SCALE);
            ps0 += s[i][0] + s[i][1];
            ps1 += s[i][2] + s[i][3];
        }
        l0 = l0 * a0 + ps0;
        l1 = l1 * a1 + ps1;
        #pragma unroll
        for (int i = 0; i < 16; i++) {
            o[i][0] *= a0; o[i][1] *= a0; o[i][2] *= a1; o[i][3] *= a1;
        }

        #pragma unroll
        for (int ks = 0; ks < 8; ks++) {
            uint32_t pa[4];
            pa[0] = pack_f16x2(s[2 * ks][0],     s[2 * ks][1]);
            pa[1] = pack_f16x2(s[2 * ks][2],     s[2 * ks][3]);
            pa[2] = pack_f16x2(s[2 * ks + 1][0], s[2 * ks + 1][1]);
            pa[3] = pack_f16x2(s[2 * ks + 1][2], s[2 * ks + 1][3]);
            #pragma unroll
            for (int ng = 0; ng < 8; ng++) {
                uint32_t addr = sb + OFF_V + bufo + (ng * 16 + (lane & 15)) * FT_ROWB
                              + ((lane >> 4) << 4) + ks * 32;
                uint32_t vf4[4];
                ldm_x4(vf4, addr);
                mma_f16(o[2 * ng],     pa, vf4[0], vf4[2]);
                mma_f16(o[2 * ng + 1], pa, vf4[1], vf4[3]);
            }
        }

        __syncthreads();
        if (j + 2 < 16) {
            fa_load_one(sb + OFF_K + bufo, g_kf,
                        kbase + (size_t)(j + 2) * 128 * NC, NC, tid);
            fa_load_one(sb + OFF_V + bufo, g_vtf,
                        vbase + (size_t)(j + 2) * 128, NS, tid);
            cp_commit();
        }
    }

    l0 += __shfl_xor_sync(0xffffffffu, l0, 1);
    l0 += __shfl_xor_sync(0xffffffffu, l0, 2);
    l1 += __shfl_xor_sync(0xffffffffu, l1, 1);
    l1 += __shfl_xor_sync(0xffffffffu, l1, 2);
    float i0 = 1.0f / l0, i1 = 1.0f / l1;

    size_t gr0 = (size_t)(b * NS + q0 + warp * 16 + (lane >> 2));
    #pragma unroll
    for (int nt = 0; nt < 16; nt++) {
        int c = h * ND + nt * 8 + (lane & 3) * 2;
        f16 h0, h1, lo0, lo1;
        split2f(o[nt][0] * i0, h0, lo0);
        split2f(o[nt][1] * i0, h1, lo1);
        *(__half2*)(g_chf + gr0 * NC + c) = __half2{h0, h1};
        *(__half2*)(g_clf + gr0 * NC + c) = __half2{lo0, lo1};
        split2f(o[nt][2] * i1, h0, lo0);
        split2f(o[nt][3] * i1, h1, lo1);
        *(__half2*)(g_chf + (gr0 + 8) * NC + c) = __half2{h0, h1};
        *(__half2*)(g_clf + (gr0 + 8) * NC + c) = __half2{lo0, lo1};
    }
}

// ---------------- elementwise kernels ----------------
__global__ __launch_bounds__(256) void cvt_split_f16(const float* __restrict__ src,
                                                     f16* __restrict__ hi,
                                                     f16* __restrict__ lo)
{
    size_t i = (size_t)blockIdx.x * 256 + threadIdx.x;
    float4 v = ((const float4*)src)[i];
    f16 h0, h1, h2, h3, l0, l1, l2, l3;
    split2f(v.x, h0, l0); split2f(v.y, h1, l1);
    split2f(v.z, h2, l2); split2f(v.w, h3, l3);
    __half2* hp = (__half2*)hi;
    __half2* lp = (__half2*)lo;
    hp[2 * i]     = __half2{h0, h1};
    hp[2 * i + 1] = __half2{h2, h3};
    lp[2 * i]     = __half2{l0, l1};
    lp[2 * i + 1] = __half2{l2, l3};
}

// Convert the 4 weight matrices in one launch: blockIdx.y selects tensor.
__global__ __launch_bounds__(256) void cvt_f16_w(
    const float* __restrict__ s0, const float* __restrict__ s1,
    const float* __restrict__ s2, const float* __restrict__ s3,
    f16* __restrict__ d0, f16* __restrict__ d1,
    f16* __restrict__ d2, f16* __restrict__ d3)
{
    const float* src = (blockIdx.y == 0) ? s0 : (blockIdx.y == 1) ? s1
                     : (blockIdx.y == 2) ? s2 : s3;
    f16* dst = (blockIdx.y == 0) ? d0 : (blockIdx.y == 1) ? d1
             : (blockIdx.y == 2) ? d2 : d3;
    size_t i = (size_t)blockIdx.x * 256 + threadIdx.x;
    float4 v = ((const float4*)src)[i];
    __half2* dp = (__half2*)dst;
    dp[2 * i]     = __floats2half2_rn(v.x, v.y);
    dp[2 * i + 1] = __floats2half2_rn(v.z, v.w);
}

// ---------------- launch ----------------
extern "C" void kernel_launch(void* const* d_in, const int* in_sizes, int n_in,
                              void* d_out, int out_size)
{
    const float* x    = (const float*)d_in[0];
    const float* rope = (const float*)d_in[1];
    const float* Wq   = (const float*)d_in[2];
    const float* bq   = (const float*)d_in[3];
    const float* Wk   = (const float*)d_in[4];
    const float* bk   = (const float*)d_in[5];
    const float* Wv   = (const float*)d_in[6];
    const float* bv   = (const float*)d_in[7];
    const float* gq   = (const float*)d_in[8];
    const float* gk   = (const float*)d_in[9];
    const float* Wo   = (const float*)d_in[10];
    const float* bo   = (const float*)d_in[11];
    float* out = (float*)d_out;

    cudaFuncSetAttribute(k_gemm_qkv, cudaFuncAttributeMaxDynamicSharedMemorySize, F16_SMEM);
    cudaFuncSetAttribute(k_gemm_out, cudaFuncAttributeMaxDynamicSharedMemorySize, F16_SMEM);
    cudaFuncSetAttribute(k_flash, cudaFuncAttributeMaxDynamicSharedMemorySize, FLASH_SMEM);

    f16 *xhf, *xlf, *wqf, *wkf, *wvf, *wof, *chf, *clf, *qhf, *qlf, *kf, *vtf;
    cudaGetSymbolAddress((void**)&xhf, g_xhf); cudaGetSymbolAddress((void**)&xlf, g_xlf);
    cudaGetSymbolAddress((void**)&wqf, g_wqf); cudaGetSymbolAddress((void**)&wkf, g_wkf);
    cudaGetSymbolAddress((void**)&wvf, g_wvf); cudaGetSymbolAddress((void**)&wof, g_wof);
    cudaGetSymbolAddress((void**)&chf, g_chf); cudaGetSymbolAddress((void**)&clf, g_clf);
    cudaGetSymbolAddress((void**)&qhf, g_qhf); cudaGetSymbolAddress((void**)&qlf, g_qlf);
    cudaGetSymbolAddress((void**)&kf, g_kf);   cudaGetSymbolAddress((void**)&vtf, g_vtf);

    const size_t nX = (size_t)NM * NC;       // 8M elems
    const size_t nW = (size_t)NC * NC;       // 4M elems

    cvt_split_f16<<<(unsigned)(nX / 1024), 256>>>(x, xhf, xlf);
    cvt_f16_w<<<dim3((unsigned)(nW / 1024), 4), 256>>>(Wq, Wk, Wv, Wo,
                                                       wqf, wkf, wvf, wof);

    // Fused Q/K/V: one launch, grid.z = operand
    k_gemm_qkv<<<dim3(NC / 128, NM / 128, 3), 256, F16_SMEM>>>(
        xhf, xlf, wqf, wkf, wvf, bq, bk, bv,
        qhf, qlf, kf, vtf, rope, gq, gk);

    k_flash<<<dim3(NS / 128, NBH), 256, FLASH_SMEM>>>();

    // out-proj: plain fp32 to harness output
    k_gemm_out<<<dim3(NC / 128, NM / 128), 256, F16_SMEM>>>(chf, clf, wof, bo, out);
}